// round 1
// baseline (speedup 1.0000x reference)
#include <cuda_runtime.h>
#include <math.h>

// Problem constants
#define BB 4
#define NN 4096
#define CC 128

// Scratch for the GELU'd q,k,v projections: [3][B*N][C] fp32 = 24 MB
__device__ float g_qkv[3][BB * NN * CC];

// ---------------------------------------------------------------------------
// Projection: out[r][d] = gelu( sum_c x[r][c] * W[d][c] + b[d] )
// One block = 32 rows of x, 128 threads (one output dim each).
// ---------------------------------------------------------------------------
__global__ __launch_bounds__(128) void proj_kernel(
    const float* __restrict__ x,
    const float* __restrict__ W,
    const float* __restrict__ bias,
    int which)
{
    __shared__ float xs[32 * 128];

    float* out = g_qkv[which];
    const int row0 = blockIdx.x * 32;
    const int tid = threadIdx.x;

    // Stage 32x128 x-tile into shared (float4, fully coalesced)
    {
        const float4* xg = (const float4*)(x + row0 * 128);
        float4* xs4 = (float4*)xs;
        #pragma unroll
        for (int i = 0; i < 8; i++) xs4[tid + i * 128] = xg[tid + i * 128];
    }
    __syncthreads();

    const int d = tid;
    const float4* w4 = (const float4*)(W + d * 128);

    float acc[32];
    #pragma unroll
    for (int r = 0; r < 32; r++) acc[r] = 0.0f;

    #pragma unroll
    for (int c0 = 0; c0 < 128; c0 += 32) {
        // Load 32 W coefficients for this chunk into registers
        float w[32];
        #pragma unroll
        for (int i = 0; i < 8; i++) {
            float4 t = w4[c0 / 4 + i];
            w[4 * i + 0] = t.x; w[4 * i + 1] = t.y;
            w[4 * i + 2] = t.z; w[4 * i + 3] = t.w;
        }
        #pragma unroll
        for (int r = 0; r < 32; r++) {
            const float4* xr4 = (const float4*)&xs[r * 128 + c0];
            float a = acc[r];
            #pragma unroll
            for (int i = 0; i < 8; i++) {
                float4 xv = xr4[i];
                a += xv.x * w[4 * i + 0];
                a += xv.y * w[4 * i + 1];
                a += xv.z * w[4 * i + 2];
                a += xv.w * w[4 * i + 3];
            }
            acc[r] = a;
        }
    }

    const float b = bias[d];
    for (int r = 0; r < 32; r++) {
        float v = acc[r] + b;
        // exact GELU (erf form)
        float g = 0.5f * v * (1.0f + erff(v * 0.70710678118654752440f));
        out[(row0 + r) * 128 + d] = g;
    }
}

// ---------------------------------------------------------------------------
// Flash attention (fp32, unscaled scores):
//   out = softmax(Q K^T) V  per batch, N=4096, d=128
// BM=64 query rows per block, BN=32 keys per tile, 256 threads.
// Thread grid 16x16: ty owns 4 query rows, tx owns 2 key cols (S phase)
// and 8 output dims (PV phase).
// ---------------------------------------------------------------------------
#define PAD_Q 68   // Qt[c][m], m-stride (64 + 4)
#define PAD_K 34   // Kt[c][n], n-stride (32 + 2)
#define PAD_V 132  // Vs[k][d], d-stride (128 + 4)
#define PAD_P 68   // Pt[k][r], r-stride (64 + 4)

#define SMEM_FLOATS (128 * PAD_Q + 128 * PAD_K + 32 * PAD_V + 32 * PAD_P)

__global__ __launch_bounds__(256, 2) void attn_kernel(float* __restrict__ out)
{
    extern __shared__ float sm[];
    float* Qt = sm;                       // [128][PAD_Q]
    float* Kt = Qt + 128 * PAD_Q;         // [128][PAD_K]
    float* Vs = Kt + 128 * PAD_K;         // [32][PAD_V]
    float* Pt = Vs + 32 * PAD_V;          // [32][PAD_P]

    const int tid = threadIdx.x;
    const int tx = tid & 15;
    const int ty = tid >> 4;

    const int b = blockIdx.x >> 6;                 // 64 blocks per batch
    const float* gq = g_qkv[0] + (size_t)blockIdx.x * 64 * 128;
    const float* gk = g_qkv[1] + (size_t)b * NN * 128;
    const float* gv = g_qkv[2] + (size_t)b * NN * 128;

    // Load Q tile (64x128) transposed into Qt[c][m]
    {
        const float4* src = (const float4*)gq;
        #pragma unroll
        for (int it = 0; it < 8; it++) {
            int i = tid + it * 256;
            int row = i >> 5;           // 0..63
            int c = (i & 31) * 4;       // 0..124
            float4 v = src[i];
            Qt[(c + 0) * PAD_Q + row] = v.x;
            Qt[(c + 1) * PAD_Q + row] = v.y;
            Qt[(c + 2) * PAD_Q + row] = v.z;
            Qt[(c + 3) * PAD_Q + row] = v.w;
        }
    }

    float accO[4][8];
    #pragma unroll
    for (int i = 0; i < 4; i++)
        #pragma unroll
        for (int j = 0; j < 8; j++) accO[i][j] = 0.0f;

    float mrow[4], lrow[4];
    #pragma unroll
    for (int i = 0; i < 4; i++) { mrow[i] = -1e30f; lrow[i] = 0.0f; }

    for (int t = 0; t < NN / 32; t++) {
        __syncthreads();  // protect Kt/Vs/Pt reuse against previous PV reads

        // Load K tile (32x128) transposed -> Kt[c][n];  V tile -> Vs[k][d]
        {
            const float4* ks = (const float4*)(gk + t * 32 * 128);
            const float4* vs = (const float4*)(gv + t * 32 * 128);
            #pragma unroll
            for (int it = 0; it < 4; it++) {
                int i = tid + it * 256;
                int row = i >> 5;        // 0..31
                int c = (i & 31) * 4;
                float4 kv = ks[i];
                Kt[(c + 0) * PAD_K + row] = kv.x;
                Kt[(c + 1) * PAD_K + row] = kv.y;
                Kt[(c + 2) * PAD_K + row] = kv.z;
                Kt[(c + 3) * PAD_K + row] = kv.w;
                float4 vv = vs[i];
                *(float4*)&Vs[row * PAD_V + c] = vv;
            }
        }
        __syncthreads();

        // S = Q K^T  (4 rows x 2 cols per thread)
        float s[4][2];
        #pragma unroll
        for (int i = 0; i < 4; i++) { s[i][0] = 0.0f; s[i][1] = 0.0f; }

        #pragma unroll 4
        for (int c = 0; c < 128; c++) {
            float4 q = *(const float4*)&Qt[c * PAD_Q + 4 * ty];
            float2 k = *(const float2*)&Kt[c * PAD_K + 2 * tx];
            s[0][0] += q.x * k.x;  s[0][1] += q.x * k.y;
            s[1][0] += q.y * k.x;  s[1][1] += q.y * k.y;
            s[2][0] += q.z * k.x;  s[2][1] += q.z * k.y;
            s[3][0] += q.w * k.x;  s[3][1] += q.w * k.y;
        }

        // Online softmax update per query row (16 tx-lanes share a row)
        #pragma unroll
        for (int i = 0; i < 4; i++) {
            float rm = fmaxf(s[i][0], s[i][1]);
            #pragma unroll
            for (int off = 8; off >= 1; off >>= 1)
                rm = fmaxf(rm, __shfl_xor_sync(0xffffffffu, rm, off, 16));
            float nm = fmaxf(mrow[i], rm);
            float scale = __expf(mrow[i] - nm);
            float p0 = __expf(s[i][0] - nm);
            float p1 = __expf(s[i][1] - nm);
            float rs = p0 + p1;
            #pragma unroll
            for (int off = 8; off >= 1; off >>= 1)
                rs += __shfl_xor_sync(0xffffffffu, rs, off, 16);
            lrow[i] = lrow[i] * scale + rs;
            mrow[i] = nm;
            #pragma unroll
            for (int dd = 0; dd < 8; dd++) accO[i][dd] *= scale;
            Pt[(2 * tx + 0) * PAD_P + 4 * ty + i] = p0;
            Pt[(2 * tx + 1) * PAD_P + 4 * ty + i] = p1;
        }
        __syncthreads();

        // O += P V  (4 rows x 8 dims per thread)
        #pragma unroll 2
        for (int k = 0; k < 32; k++) {
            float4 p  = *(const float4*)&Pt[k * PAD_P + 4 * ty];
            float4 va = *(const float4*)&Vs[k * PAD_V + 8 * tx];
            float4 vb = *(const float4*)&Vs[k * PAD_V + 8 * tx + 4];
            float pv[4] = {p.x, p.y, p.z, p.w};
            float vv[8] = {va.x, va.y, va.z, va.w, vb.x, vb.y, vb.z, vb.w};
            #pragma unroll
            for (int i = 0; i < 4; i++)
                #pragma unroll
                for (int dd = 0; dd < 8; dd++)
                    accO[i][dd] += pv[i] * vv[dd];
        }
    }

    // Epilogue: normalize and store
    #pragma unroll
    for (int i = 0; i < 4; i++) {
        float inv = 1.0f / lrow[i];
        size_t row = (size_t)blockIdx.x * 64 + 4 * ty + i;
        float4 o1 = make_float4(accO[i][0] * inv, accO[i][1] * inv,
                                accO[i][2] * inv, accO[i][3] * inv);
        float4 o2 = make_float4(accO[i][4] * inv, accO[i][5] * inv,
                                accO[i][6] * inv, accO[i][7] * inv);
        *(float4*)&out[row * 128 + 8 * tx] = o1;
        *(float4*)&out[row * 128 + 8 * tx + 4] = o2;
    }
}

// ---------------------------------------------------------------------------
extern "C" void kernel_launch(void* const* d_in, const int* in_sizes, int n_in,
                              void* d_out, int out_size)
{
    (void)in_sizes; (void)n_in; (void)out_size;
    const float* x  = (const float*)d_in[0];
    const float* Wq = (const float*)d_in[1];
    const float* bq = (const float*)d_in[2];
    const float* Wk = (const float*)d_in[3];
    const float* bk = (const float*)d_in[4];
    const float* Wv = (const float*)d_in[5];
    const float* bv = (const float*)d_in[6];
    float* out = (float*)d_out;

    cudaFuncSetAttribute(attn_kernel,
                         cudaFuncAttributeMaxDynamicSharedMemorySize,
                         SMEM_FLOATS * (int)sizeof(float));

    dim3 pgrid(BB * NN / 32);
    proj_kernel<<<pgrid, 128>>>(x, Wq, bq, 0);
    proj_kernel<<<pgrid, 128>>>(x, Wk, bk, 1);
    proj_kernel<<<pgrid, 128>>>(x, Wv, bv, 2);

    attn_kernel<<<BB * NN / 64, 256, SMEM_FLOATS * sizeof(float)>>>(out);
}

// round 3
// speedup vs baseline: 3.8962x; 3.8962x over previous
#include <cuda_runtime.h>
#include <cuda_bf16.h>
#include <math.h>
#include <stdint.h>

#define BB 4
#define NN 4096
#define CC 128

// Pre-split bf16 hi/lo projections (q,k,v) — written by proj, read by attn.
__device__ __nv_bfloat16 g_qh[BB * NN * CC];
__device__ __nv_bfloat16 g_ql[BB * NN * CC];
__device__ __nv_bfloat16 g_kh[BB * NN * CC];
__device__ __nv_bfloat16 g_kl[BB * NN * CC];
__device__ __nv_bfloat16 g_vh[BB * NN * CC];
__device__ __nv_bfloat16 g_vl[BB * NN * CC];

// ---------------------------------------------------------------------------
// Projection: gelu(x W^T + b), split into bf16 hi + lo residual.
// ---------------------------------------------------------------------------
__global__ __launch_bounds__(128) void proj_kernel(
    const float* __restrict__ x,
    const float* __restrict__ W,
    const float* __restrict__ bias,
    int which)
{
    __shared__ float xs[32 * 128];

    __nv_bfloat16 *oh, *ol;
    if (which == 0)      { oh = g_qh; ol = g_ql; }
    else if (which == 1) { oh = g_kh; ol = g_kl; }
    else                 { oh = g_vh; ol = g_vl; }

    const int row0 = blockIdx.x * 32;
    const int tid = threadIdx.x;

    {
        const float4* xg = (const float4*)(x + row0 * 128);
        float4* xs4 = (float4*)xs;
        #pragma unroll
        for (int i = 0; i < 8; i++) xs4[tid + i * 128] = xg[tid + i * 128];
    }
    __syncthreads();

    const int d = tid;
    const float4* w4 = (const float4*)(W + d * 128);

    float acc[32];
    #pragma unroll
    for (int r = 0; r < 32; r++) acc[r] = 0.0f;

    #pragma unroll
    for (int c0 = 0; c0 < 128; c0 += 32) {
        float w[32];
        #pragma unroll
        for (int i = 0; i < 8; i++) {
            float4 t = w4[c0 / 4 + i];
            w[4 * i + 0] = t.x; w[4 * i + 1] = t.y;
            w[4 * i + 2] = t.z; w[4 * i + 3] = t.w;
        }
        #pragma unroll
        for (int r = 0; r < 32; r++) {
            const float4* xr4 = (const float4*)&xs[r * 128 + c0];
            float a = acc[r];
            #pragma unroll
            for (int i = 0; i < 8; i++) {
                float4 xv = xr4[i];
                a += xv.x * w[4 * i + 0];
                a += xv.y * w[4 * i + 1];
                a += xv.z * w[4 * i + 2];
                a += xv.w * w[4 * i + 3];
            }
            acc[r] = a;
        }
    }

    const float b = bias[d];
    for (int r = 0; r < 32; r++) {
        float v = acc[r] + b;
        float g = 0.5f * v * (1.0f + erff(v * 0.70710678118654752440f));
        __nv_bfloat16 hi = __float2bfloat16(g);
        __nv_bfloat16 lo = __float2bfloat16(g - __bfloat162float(hi));
        oh[(row0 + r) * 128 + d] = hi;
        ol[(row0 + r) * 128 + d] = lo;
    }
}

// ---------------------------------------------------------------------------
// PTX helpers (all compute_103-baseline features)
// ---------------------------------------------------------------------------
__device__ __forceinline__ uint32_t smem_u32(const void* p) {
    uint32_t a;
    asm("{ .reg .u64 t; cvta.to.shared.u64 t, %1; cvt.u32.u64 %0, t; }"
        : "=r"(a) : "l"(p));
    return a;
}

__device__ __forceinline__ void ldsm4(uint32_t a, uint32_t r[4]) {
    asm volatile("ldmatrix.sync.aligned.m8n8.x4.shared.b16 {%0,%1,%2,%3}, [%4];"
        : "=r"(r[0]), "=r"(r[1]), "=r"(r[2]), "=r"(r[3]) : "r"(a));
}
__device__ __forceinline__ void ldsm4t(uint32_t a, uint32_t r[4]) {
    asm volatile("ldmatrix.sync.aligned.m8n8.x4.trans.shared.b16 {%0,%1,%2,%3}, [%4];"
        : "=r"(r[0]), "=r"(r[1]), "=r"(r[2]), "=r"(r[3]) : "r"(a));
}
__device__ __forceinline__ void mma_bf16(float c[4], const uint32_t a[4],
                                         uint32_t b0, uint32_t b1) {
    asm volatile(
        "mma.sync.aligned.m16n8k16.row.col.f32.bf16.bf16.f32 "
        "{%0,%1,%2,%3}, {%4,%5,%6,%7}, {%8,%9}, {%0,%1,%2,%3};"
        : "+f"(c[0]), "+f"(c[1]), "+f"(c[2]), "+f"(c[3])
        : "r"(a[0]), "r"(a[1]), "r"(a[2]), "r"(a[3]), "r"(b0), "r"(b1));
}
__device__ __forceinline__ void cpa16(uint32_t dst, const void* src) {
    asm volatile("cp.async.cg.shared.global [%0], [%1], 16;" :: "r"(dst), "l"(src));
}
#define CPA_COMMIT() asm volatile("cp.async.commit_group;" ::: "memory")
#define CPA_WAIT0()  asm volatile("cp.async.wait_group 0;" ::: "memory")

__device__ __forceinline__ uint32_t packbf(__nv_bfloat16 a, __nv_bfloat16 b) {
    return (uint32_t)__bfloat16_as_ushort(a)
         | ((uint32_t)__bfloat16_as_ushort(b) << 16);
}

// ---------------------------------------------------------------------------
// Flash attention via mma.sync bf16 3-pass split.
//   CTA: 128 q rows, 8 warps (m16 each). Key tiles of 64, double-buffered.
// ---------------------------------------------------------------------------
#define QSTR 272                 // smem row stride (bytes): conflict-free ldmatrix
#define SM_QH 0                  // 128 * 272 = 34816
#define SM_QL 34816
#define SM_KV 69632              // 2 stages of {KH,KL,VH,VL}, each 64*272
#define STG   69632              // bytes per stage (4 * 17408)
#define KHOF  0
#define KLOF  17408
#define VHOF  34816
#define VLOF  52224
#define SM_TOTAL (SM_KV + 2 * STG)   // 208896

__global__ __launch_bounds__(256, 1) void attn_mma_kernel(float* __restrict__ out)
{
    extern __shared__ char sm[];
    const uint32_t sb = smem_u32(sm);
    const int tid = threadIdx.x;
    const int w = tid >> 5;
    const int lane = tid & 31;

    const int bid = blockIdx.x;
    const int batch = bid >> 5;
    const size_t qoff = (size_t)bid * 128 * CC;
    const size_t kvoff = (size_t)batch * NN * CC;

    // ---- async-load Q (hi+lo) and KV tile 0
    #pragma unroll
    for (int i = 0; i < 8; i++) {
        int cid = tid + i * 256;          // 2048 chunks per Q buffer
        int r = cid >> 4, c = cid & 15;
        uint32_t d = (uint32_t)(r * QSTR + c * 16);
        const __nv_bfloat16* s = g_qh + qoff + r * 128 + c * 8;
        cpa16(sb + SM_QH + d, s);
        cpa16(sb + SM_QL + d, g_ql + qoff + r * 128 + c * 8);
    }
    {
        uint32_t base = sb + SM_KV;       // stage 0
        #pragma unroll
        for (int i = 0; i < 4; i++) {
            int cid = tid + i * 256;      // 1024 chunks per buffer
            int r = cid >> 4, c = cid & 15;
            uint32_t d = base + r * QSTR + c * 16;
            size_t g = kvoff + (size_t)r * 128 + c * 8;
            cpa16(d + KHOF, g_kh + g);
            cpa16(d + KLOF, g_kl + g);
            cpa16(d + VHOF, g_vh + g);
            cpa16(d + VLOF, g_vl + g);
        }
    }
    CPA_COMMIT();

    float O[16][4];
    #pragma unroll
    for (int j = 0; j < 16; j++)
        #pragma unroll
        for (int q = 0; q < 4; q++) O[j][q] = 0.0f;
    float m0 = -1e30f, m1 = -1e30f, l0 = 0.0f, l1 = 0.0f;

    const int R = w * 16;
    // precomputed ldmatrix lane-address components
    const uint32_t q_lrow = (uint32_t)((R + (lane & 15)) * QSTR + ((lane >> 4) << 4));
    const uint32_t k_lrow = (uint32_t)(((lane & 7) + ((lane >> 4) << 3)) * QSTR
                                       + (((lane >> 3) & 1) << 4));
    const uint32_t v_lrow = (uint32_t)(((lane & 7) + (((lane >> 3) & 1) << 3)) * QSTR
                                       + ((lane >> 4) << 4));

    CPA_WAIT0();
    __syncthreads();

    for (int t = 0; t < NN / 64; t++) {
        // ---- prefetch next KV tile into the other stage
        if (t + 1 < NN / 64) {
            uint32_t base = sb + SM_KV + ((t + 1) & 1) * STG;
            size_t gkv = kvoff + (size_t)(t + 1) * 64 * 128;
            #pragma unroll
            for (int i = 0; i < 4; i++) {
                int cid = tid + i * 256;
                int r = cid >> 4, c = cid & 15;
                uint32_t d = base + r * QSTR + c * 16;
                size_t g = gkv + (size_t)r * 128 + c * 8;
                cpa16(d + KHOF, g_kh + g);
                cpa16(d + KLOF, g_kl + g);
                cpa16(d + VHOF, g_vh + g);
                cpa16(d + VLOF, g_vl + g);
            }
            CPA_COMMIT();
        }

        const uint32_t kb = sb + SM_KV + (t & 1) * STG;

        // ---- S = Q K^T, 3-pass split, fp32 accum in registers
        float S[8][4];
        #pragma unroll
        for (int j = 0; j < 8; j++)
            #pragma unroll
            for (int q = 0; q < 4; q++) S[j][q] = 0.0f;

        #pragma unroll
        for (int c = 0; c < 8; c++) {
            uint32_t aQh[4], aQl[4];
            ldsm4(sb + SM_QH + q_lrow + 32 * c, aQh);
            ldsm4(sb + SM_QL + q_lrow + 32 * c, aQl);
            #pragma unroll
            for (int jg = 0; jg < 4; jg++) {
                uint32_t bh[4], bl[4];
                uint32_t ka = kb + KHOF + (uint32_t)(jg * 16 * QSTR) + k_lrow + 32 * c;
                ldsm4(ka, bh);
                ldsm4(ka + (KLOF - KHOF), bl);
                mma_bf16(S[2 * jg],     aQh, bh[0], bh[1]);
                mma_bf16(S[2 * jg],     aQh, bl[0], bl[1]);
                mma_bf16(S[2 * jg],     aQl, bh[0], bh[1]);
                mma_bf16(S[2 * jg + 1], aQh, bh[2], bh[3]);
                mma_bf16(S[2 * jg + 1], aQh, bl[2], bl[3]);
                mma_bf16(S[2 * jg + 1], aQl, bh[2], bh[3]);
            }
        }

        // ---- online softmax (rows r=lane/4 and r+8; cols spread over quad)
        float mx0 = S[0][0], mx1 = S[0][2];
        #pragma unroll
        for (int j = 0; j < 8; j++) {
            mx0 = fmaxf(mx0, fmaxf(S[j][0], S[j][1]));
            mx1 = fmaxf(mx1, fmaxf(S[j][2], S[j][3]));
        }
        #pragma unroll
        for (int off = 1; off <= 2; off <<= 1) {
            mx0 = fmaxf(mx0, __shfl_xor_sync(0xffffffffu, mx0, off));
            mx1 = fmaxf(mx1, __shfl_xor_sync(0xffffffffu, mx1, off));
        }
        float mn0 = fmaxf(m0, mx0), mn1 = fmaxf(m1, mx1);
        float cr0 = __expf(m0 - mn0), cr1 = __expf(m1 - mn1);
        m0 = mn0; m1 = mn1;

        float s0 = 0.0f, s1 = 0.0f;
        #pragma unroll
        for (int j = 0; j < 8; j++) {
            S[j][0] = __expf(S[j][0] - mn0); s0 += S[j][0];
            S[j][1] = __expf(S[j][1] - mn0); s0 += S[j][1];
            S[j][2] = __expf(S[j][2] - mn1); s1 += S[j][2];
            S[j][3] = __expf(S[j][3] - mn1); s1 += S[j][3];
        }
        #pragma unroll
        for (int off = 1; off <= 2; off <<= 1) {
            s0 += __shfl_xor_sync(0xffffffffu, s0, off);
            s1 += __shfl_xor_sync(0xffffffffu, s1, off);
        }
        l0 = l0 * cr0 + s0;
        l1 = l1 * cr1 + s1;

        #pragma unroll
        for (int j = 0; j < 16; j++) {
            O[j][0] *= cr0; O[j][1] *= cr0;
            O[j][2] *= cr1; O[j][3] *= cr1;
        }

        // ---- pack P into bf16 hi/lo A-fragments (register-only)
        uint32_t ph[4][4], pl[4][4];
        #pragma unroll
        for (int c = 0; c < 4; c++) {
            #pragma unroll
            for (int half = 0; half < 2; half++) {     // tiles 2c, 2c+1
                const float* sv = S[2 * c + half];
                __nv_bfloat16 h0 = __float2bfloat16(sv[0]);
                __nv_bfloat16 h1 = __float2bfloat16(sv[1]);
                __nv_bfloat16 h2 = __float2bfloat16(sv[2]);
                __nv_bfloat16 h3 = __float2bfloat16(sv[3]);
                ph[c][2 * half + 0] = packbf(h0, h1);
                ph[c][2 * half + 1] = packbf(h2, h3);
                pl[c][2 * half + 0] = packbf(
                    __float2bfloat16(sv[0] - __bfloat162float(h0)),
                    __float2bfloat16(sv[1] - __bfloat162float(h1)));
                pl[c][2 * half + 1] = packbf(
                    __float2bfloat16(sv[2] - __bfloat162float(h2)),
                    __float2bfloat16(sv[3] - __bfloat162float(h3)));
            }
        }

        // ---- O += P V, 3-pass split; V transposed for free via ldmatrix.trans
        #pragma unroll
        for (int c = 0; c < 4; c++) {
            #pragma unroll
            for (int jg = 0; jg < 8; jg++) {
                uint32_t vh[4], vl[4];
                uint32_t va = kb + VHOF + (uint32_t)(16 * c * QSTR) + v_lrow + 32 * jg;
                ldsm4t(va, vh);
                ldsm4t(va + (VLOF - VHOF), vl);
                mma_bf16(O[2 * jg],     ph[c], vh[0], vh[1]);
                mma_bf16(O[2 * jg],     ph[c], vl[0], vl[1]);
                mma_bf16(O[2 * jg],     pl[c], vh[0], vh[1]);
                mma_bf16(O[2 * jg + 1], ph[c], vh[2], vh[3]);
                mma_bf16(O[2 * jg + 1], ph[c], vl[2], vl[3]);
                mma_bf16(O[2 * jg + 1], pl[c], vh[2], vh[3]);
            }
        }

        if (t + 1 < NN / 64) {
            CPA_WAIT0();
            __syncthreads();
        }
    }

    // ---- epilogue
    {
        float inv0 = 1.0f / l0, inv1 = 1.0f / l1;
        size_t gr0 = (size_t)bid * 128 + R + (lane >> 2);
        size_t gr1 = gr0 + 8;
        int colb = (lane & 3) * 2;
        #pragma unroll
        for (int j = 0; j < 16; j++) {
            int col = 8 * j + colb;
            *(float2*)&out[gr0 * 128 + col] = make_float2(O[j][0] * inv0, O[j][1] * inv0);
            *(float2*)&out[gr1 * 128 + col] = make_float2(O[j][2] * inv1, O[j][3] * inv1);
        }
    }
}

// ---------------------------------------------------------------------------
extern "C" void kernel_launch(void* const* d_in, const int* in_sizes, int n_in,
                              void* d_out, int out_size)
{
    (void)in_sizes; (void)n_in; (void)out_size;
    const float* x  = (const float*)d_in[0];
    const float* Wq = (const float*)d_in[1];
    const float* bq = (const float*)d_in[2];
    const float* Wk = (const float*)d_in[3];
    const float* bk = (const float*)d_in[4];
    const float* Wv = (const float*)d_in[5];
    const float* bv = (const float*)d_in[6];
    float* out = (float*)d_out;

    cudaFuncSetAttribute(attn_mma_kernel,
                         cudaFuncAttributeMaxDynamicSharedMemorySize, SM_TOTAL);

    dim3 pgrid(BB * NN / 32);
    proj_kernel<<<pgrid, 128>>>(x, Wq, bq, 0);
    proj_kernel<<<pgrid, 128>>>(x, Wk, bk, 1);
    proj_kernel<<<pgrid, 128>>>(x, Wv, bv, 2);

    attn_mma_kernel<<<BB * NN / 128, 256, SM_TOTAL>>>(out);
}

// round 4
// speedup vs baseline: 4.6174x; 1.1851x over previous
#include <cuda_runtime.h>
#include <cuda_bf16.h>
#include <math.h>
#include <stdint.h>

#define BB 4
#define NN 4096
#define CC 128

// Pre-split bf16 hi/lo projections (q,k,v) — written by proj, read by attn.
__device__ __nv_bfloat16 g_qh[BB * NN * CC];
__device__ __nv_bfloat16 g_ql[BB * NN * CC];
__device__ __nv_bfloat16 g_kh[BB * NN * CC];
__device__ __nv_bfloat16 g_kl[BB * NN * CC];
__device__ __nv_bfloat16 g_vh[BB * NN * CC];
__device__ __nv_bfloat16 g_vl[BB * NN * CC];

// Pre-split weights: [which][d*128+c]
__device__ __nv_bfloat16 g_wh[3][CC * CC];
__device__ __nv_bfloat16 g_wl[3][CC * CC];

// ---------------------------------------------------------------------------
// PTX helpers (compute_103-baseline features only)
// ---------------------------------------------------------------------------
__device__ __forceinline__ uint32_t smem_u32(const void* p) {
    uint32_t a;
    asm("{ .reg .u64 t; cvta.to.shared.u64 t, %1; cvt.u32.u64 %0, t; }"
        : "=r"(a) : "l"(p));
    return a;
}
__device__ __forceinline__ void ldsm4(uint32_t a, uint32_t r[4]) {
    asm volatile("ldmatrix.sync.aligned.m8n8.x4.shared.b16 {%0,%1,%2,%3}, [%4];"
        : "=r"(r[0]), "=r"(r[1]), "=r"(r[2]), "=r"(r[3]) : "r"(a));
}
__device__ __forceinline__ void ldsm4t(uint32_t a, uint32_t r[4]) {
    asm volatile("ldmatrix.sync.aligned.m8n8.x4.trans.shared.b16 {%0,%1,%2,%3}, [%4];"
        : "=r"(r[0]), "=r"(r[1]), "=r"(r[2]), "=r"(r[3]) : "r"(a));
}
__device__ __forceinline__ void mma_bf16(float c[4], const uint32_t a[4],
                                         uint32_t b0, uint32_t b1) {
    asm volatile(
        "mma.sync.aligned.m16n8k16.row.col.f32.bf16.bf16.f32 "
        "{%0,%1,%2,%3}, {%4,%5,%6,%7}, {%8,%9}, {%0,%1,%2,%3};"
        : "+f"(c[0]), "+f"(c[1]), "+f"(c[2]), "+f"(c[3])
        : "r"(a[0]), "r"(a[1]), "r"(a[2]), "r"(a[3]), "r"(b0), "r"(b1));
}
__device__ __forceinline__ void cpa16(uint32_t dst, const void* src) {
    asm volatile("cp.async.cg.shared.global [%0], [%1], 16;" :: "r"(dst), "l"(src));
}
#define CPA_COMMIT() asm volatile("cp.async.commit_group;" ::: "memory")
#define CPA_WAIT(n)  asm volatile("cp.async.wait_group %0;" :: "n"(n) : "memory")

__device__ __forceinline__ uint32_t packbf(__nv_bfloat16 a, __nv_bfloat16 b) {
    return (uint32_t)__bfloat16_as_ushort(a)
         | ((uint32_t)__bfloat16_as_ushort(b) << 16);
}

#define QSTR 272   // smem row stride (bytes): conflict-free ldmatrix

// ---------------------------------------------------------------------------
// Setup: split the three weight matrices into bf16 hi/lo.
// ---------------------------------------------------------------------------
__global__ __launch_bounds__(512) void split_w_kernel(
    const float* __restrict__ Wq,
    const float* __restrict__ Wk,
    const float* __restrict__ Wv)
{
    int idx = blockIdx.x * 512 + threadIdx.x;   // 0 .. 49151
    int which = idx >> 14;
    int i = idx & 16383;
    const float* W = (which == 0) ? Wq : (which == 1) ? Wk : Wv;
    float v = W[i];
    __nv_bfloat16 hi = __float2bfloat16(v);
    g_wh[which][i] = hi;
    g_wl[which][i] = __float2bfloat16(v - __bfloat162float(hi));
}

// ---------------------------------------------------------------------------
// Fused tensor-core projection: q,k,v = split(gelu(x W^T + b))
// 128 CTAs x 256 threads; each CTA owns 128 rows of x.
// ---------------------------------------------------------------------------
#define PSM_XH 0
#define PSM_XL 34816
#define PSM_W0 69632            // {hi, lo} buffer 0
#define PSM_W1 139264           // {hi, lo} buffer 1
#define PSM_B  208896           // 3 x 128 floats
#define PSM_TOTAL (PSM_B + 1536)

__device__ __forceinline__ void proj_compute(
    uint32_t sb, uint32_t wbuf, const float* bias_s,
    __nv_bfloat16* __restrict__ oh, __nv_bfloat16* __restrict__ ol,
    int row0, int lane, uint32_t a_lrow, uint32_t b_lrow)
{
    float acc[16][4];
    #pragma unroll
    for (int j = 0; j < 16; j++)
        #pragma unroll
        for (int q = 0; q < 4; q++) acc[j][q] = 0.0f;

    #pragma unroll
    for (int c = 0; c < 8; c++) {
        uint32_t ah[4], al[4];
        ldsm4(sb + PSM_XH + a_lrow + 32 * c, ah);
        ldsm4(sb + PSM_XL + a_lrow + 32 * c, al);
        #pragma unroll
        for (int jg = 0; jg < 8; jg++) {
            uint32_t bh[4], bl[4];
            uint32_t ba = wbuf + (uint32_t)(jg * 16 * QSTR) + b_lrow + 32 * c;
            ldsm4(ba, bh);
            ldsm4(ba + 34816, bl);
            mma_bf16(acc[2 * jg],     ah, bh[0], bh[1]);
            mma_bf16(acc[2 * jg],     ah, bl[0], bl[1]);
            mma_bf16(acc[2 * jg],     al, bh[0], bh[1]);
            mma_bf16(acc[2 * jg + 1], ah, bh[2], bh[3]);
            mma_bf16(acc[2 * jg + 1], ah, bl[2], bl[3]);
            mma_bf16(acc[2 * jg + 1], al, bh[2], bh[3]);
        }
    }

    // epilogue: +bias, exact GELU, split, store
    int r0 = row0 + (lane >> 2);
    int r1 = r0 + 8;
    int colb = (lane & 3) * 2;
    #pragma unroll
    for (int j = 0; j < 16; j++) {
        int col = 8 * j + colb;
        float b0 = bias_s[col], b1 = bias_s[col + 1];
        float v00 = acc[j][0] + b0, v01 = acc[j][1] + b1;
        float v10 = acc[j][2] + b0, v11 = acc[j][3] + b1;
        float g00 = 0.5f * v00 * (1.0f + erff(v00 * 0.70710678f));
        float g01 = 0.5f * v01 * (1.0f + erff(v01 * 0.70710678f));
        float g10 = 0.5f * v10 * (1.0f + erff(v10 * 0.70710678f));
        float g11 = 0.5f * v11 * (1.0f + erff(v11 * 0.70710678f));
        __nv_bfloat16 h00 = __float2bfloat16(g00);
        __nv_bfloat16 h01 = __float2bfloat16(g01);
        __nv_bfloat16 h10 = __float2bfloat16(g10);
        __nv_bfloat16 h11 = __float2bfloat16(g11);
        *(uint32_t*)(oh + (size_t)r0 * 128 + col) = packbf(h00, h01);
        *(uint32_t*)(oh + (size_t)r1 * 128 + col) = packbf(h10, h11);
        *(uint32_t*)(ol + (size_t)r0 * 128 + col) = packbf(
            __float2bfloat16(g00 - __bfloat162float(h00)),
            __float2bfloat16(g01 - __bfloat162float(h01)));
        *(uint32_t*)(ol + (size_t)r1 * 128 + col) = packbf(
            __float2bfloat16(g10 - __bfloat162float(h10)),
            __float2bfloat16(g11 - __bfloat162float(h11)));
    }
}

__global__ __launch_bounds__(256, 1) void proj_mma_kernel(
    const float* __restrict__ x,
    const float* __restrict__ bq,
    const float* __restrict__ bk,
    const float* __restrict__ bv)
{
    extern __shared__ char sm[];
    const uint32_t sb = smem_u32(sm);
    const int tid = threadIdx.x;
    const int w = tid >> 5;
    const int lane = tid & 31;
    const int row0 = blockIdx.x * 128;

    // async-stage W0 -> buf0, W1 -> buf1 (hi + lo each)
    #pragma unroll
    for (int i = 0; i < 8; i++) {
        int cid = tid + i * 256;             // 2048 16B-chunks
        int r = cid >> 4, c = cid & 15;
        uint32_t d = (uint32_t)(r * QSTR + c * 16);
        int g = r * 128 + c * 8;
        cpa16(sb + PSM_W0 + d,         (const char*)g_wh[0] + g * 2);
        cpa16(sb + PSM_W0 + 34816 + d, (const char*)g_wl[0] + g * 2);
    }
    CPA_COMMIT();
    #pragma unroll
    for (int i = 0; i < 8; i++) {
        int cid = tid + i * 256;
        int r = cid >> 4, c = cid & 15;
        uint32_t d = (uint32_t)(r * QSTR + c * 16);
        int g = r * 128 + c * 8;
        cpa16(sb + PSM_W1 + d,         (const char*)g_wh[1] + g * 2);
        cpa16(sb + PSM_W1 + 34816 + d, (const char*)g_wl[1] + g * 2);
    }
    CPA_COMMIT();

    // stage x tile (fp32 -> bf16 hi/lo) and biases
    {
        const float4* xg = (const float4*)(x + (size_t)row0 * 128);
        #pragma unroll
        for (int i = 0; i < 16; i++) {
            int i4 = tid + i * 256;          // 4096 float4s
            int r = i4 >> 5, c = (i4 & 31) << 2;
            float4 v = xg[i4];
            uint32_t d = (uint32_t)(r * QSTR + c * 2);
            __nv_bfloat16 hx = __float2bfloat16(v.x);
            __nv_bfloat16 hy = __float2bfloat16(v.y);
            __nv_bfloat16 hz = __float2bfloat16(v.z);
            __nv_bfloat16 hw = __float2bfloat16(v.w);
            *(uint32_t*)(sm + PSM_XH + d)     = packbf(hx, hy);
            *(uint32_t*)(sm + PSM_XH + d + 4) = packbf(hz, hw);
            *(uint32_t*)(sm + PSM_XL + d) = packbf(
                __float2bfloat16(v.x - __bfloat162float(hx)),
                __float2bfloat16(v.y - __bfloat162float(hy)));
            *(uint32_t*)(sm + PSM_XL + d + 4) = packbf(
                __float2bfloat16(v.z - __bfloat162float(hz)),
                __float2bfloat16(v.w - __bfloat162float(hw)));
        }
        float* bias_s = (float*)(sm + PSM_B);
        if (tid < 128)      bias_s[tid] = bq[tid];
        else if (tid < 256) bias_s[tid] = bk[tid - 128];
        if (tid < 128)      bias_s[256 + tid] = bv[tid];
    }

    const int R = w * 16;
    const uint32_t a_lrow = (uint32_t)((R + (lane & 15)) * QSTR + ((lane >> 4) << 4));
    const uint32_t b_lrow = (uint32_t)(((lane & 7) + ((lane >> 4) << 3)) * QSTR
                                       + (((lane >> 3) & 1) << 4));
    const float* bias_s = (const float*)(sm + PSM_B);

    CPA_WAIT(1);          // W0 ready
    __syncthreads();
    proj_compute(sb, sb + PSM_W0, bias_s, g_qh, g_ql, row0 + R, lane, a_lrow, b_lrow);
    __syncthreads();      // everyone done reading buf0

    // stage W2 -> buf0
    #pragma unroll
    for (int i = 0; i < 8; i++) {
        int cid = tid + i * 256;
        int r = cid >> 4, c = cid & 15;
        uint32_t d = (uint32_t)(r * QSTR + c * 16);
        int g = r * 128 + c * 8;
        cpa16(sb + PSM_W0 + d,         (const char*)g_wh[2] + g * 2);
        cpa16(sb + PSM_W0 + 34816 + d, (const char*)g_wl[2] + g * 2);
    }
    CPA_COMMIT();

    CPA_WAIT(1);          // W1 ready
    __syncthreads();
    proj_compute(sb, sb + PSM_W1, bias_s + 128, g_kh, g_kl, row0 + R, lane, a_lrow, b_lrow);

    CPA_WAIT(0);          // W2 ready
    __syncthreads();
    proj_compute(sb, sb + PSM_W0, bias_s + 256, g_vh, g_vl, row0 + R, lane, a_lrow, b_lrow);
}

// ---------------------------------------------------------------------------
// Flash attention via mma.sync bf16 3-pass split (validated R2 version).
// ---------------------------------------------------------------------------
#define SM_QH 0
#define SM_QL 34816
#define SM_KV 69632
#define STG   69632
#define KHOF  0
#define KLOF  17408
#define VHOF  34816
#define VLOF  52224
#define SM_TOTAL (SM_KV + 2 * STG)

__global__ __launch_bounds__(256, 1) void attn_mma_kernel(float* __restrict__ out)
{
    extern __shared__ char sm[];
    const uint32_t sb = smem_u32(sm);
    const int tid = threadIdx.x;
    const int w = tid >> 5;
    const int lane = tid & 31;

    const int bid = blockIdx.x;
    const int batch = bid >> 5;
    const size_t qoff = (size_t)bid * 128 * CC;
    const size_t kvoff = (size_t)batch * NN * CC;

    #pragma unroll
    for (int i = 0; i < 8; i++) {
        int cid = tid + i * 256;
        int r = cid >> 4, c = cid & 15;
        uint32_t d = (uint32_t)(r * QSTR + c * 16);
        cpa16(sb + SM_QH + d, g_qh + qoff + r * 128 + c * 8);
        cpa16(sb + SM_QL + d, g_ql + qoff + r * 128 + c * 8);
    }
    {
        uint32_t base = sb + SM_KV;
        #pragma unroll
        for (int i = 0; i < 4; i++) {
            int cid = tid + i * 256;
            int r = cid >> 4, c = cid & 15;
            uint32_t d = base + r * QSTR + c * 16;
            size_t g = kvoff + (size_t)r * 128 + c * 8;
            cpa16(d + KHOF, g_kh + g);
            cpa16(d + KLOF, g_kl + g);
            cpa16(d + VHOF, g_vh + g);
            cpa16(d + VLOF, g_vl + g);
        }
    }
    CPA_COMMIT();

    float O[16][4];
    #pragma unroll
    for (int j = 0; j < 16; j++)
        #pragma unroll
        for (int q = 0; q < 4; q++) O[j][q] = 0.0f;
    float m0 = -1e30f, m1 = -1e30f, l0 = 0.0f, l1 = 0.0f;

    const int R = w * 16;
    const uint32_t q_lrow = (uint32_t)((R + (lane & 15)) * QSTR + ((lane >> 4) << 4));
    const uint32_t k_lrow = (uint32_t)(((lane & 7) + ((lane >> 4) << 3)) * QSTR
                                       + (((lane >> 3) & 1) << 4));
    const uint32_t v_lrow = (uint32_t)(((lane & 7) + (((lane >> 3) & 1) << 3)) * QSTR
                                       + ((lane >> 4) << 4));

    CPA_WAIT(0);
    __syncthreads();

    for (int t = 0; t < NN / 64; t++) {
        if (t + 1 < NN / 64) {
            uint32_t base = sb + SM_KV + ((t + 1) & 1) * STG;
            size_t gkv = kvoff + (size_t)(t + 1) * 64 * 128;
            #pragma unroll
            for (int i = 0; i < 4; i++) {
                int cid = tid + i * 256;
                int r = cid >> 4, c = cid & 15;
                uint32_t d = base + r * QSTR + c * 16;
                size_t g = gkv + (size_t)r * 128 + c * 8;
                cpa16(d + KHOF, g_kh + g);
                cpa16(d + KLOF, g_kl + g);
                cpa16(d + VHOF, g_vh + g);
                cpa16(d + VLOF, g_vl + g);
            }
            CPA_COMMIT();
        }

        const uint32_t kb = sb + SM_KV + (t & 1) * STG;

        float S[8][4];
        #pragma unroll
        for (int j = 0; j < 8; j++)
            #pragma unroll
            for (int q = 0; q < 4; q++) S[j][q] = 0.0f;

        #pragma unroll
        for (int c = 0; c < 8; c++) {
            uint32_t aQh[4], aQl[4];
            ldsm4(sb + SM_QH + q_lrow + 32 * c, aQh);
            ldsm4(sb + SM_QL + q_lrow + 32 * c, aQl);
            #pragma unroll
            for (int jg = 0; jg < 4; jg++) {
                uint32_t bh[4], bl[4];
                uint32_t ka = kb + KHOF + (uint32_t)(jg * 16 * QSTR) + k_lrow + 32 * c;
                ldsm4(ka, bh);
                ldsm4(ka + (KLOF - KHOF), bl);
                mma_bf16(S[2 * jg],     aQh, bh[0], bh[1]);
                mma_bf16(S[2 * jg],     aQh, bl[0], bl[1]);
                mma_bf16(S[2 * jg],     aQl, bh[0], bh[1]);
                mma_bf16(S[2 * jg + 1], aQh, bh[2], bh[3]);
                mma_bf16(S[2 * jg + 1], aQh, bl[2], bl[3]);
                mma_bf16(S[2 * jg + 1], aQl, bh[2], bh[3]);
            }
        }

        float mx0 = S[0][0], mx1 = S[0][2];
        #pragma unroll
        for (int j = 0; j < 8; j++) {
            mx0 = fmaxf(mx0, fmaxf(S[j][0], S[j][1]));
            mx1 = fmaxf(mx1, fmaxf(S[j][2], S[j][3]));
        }
        #pragma unroll
        for (int off = 1; off <= 2; off <<= 1) {
            mx0 = fmaxf(mx0, __shfl_xor_sync(0xffffffffu, mx0, off));
            mx1 = fmaxf(mx1, __shfl_xor_sync(0xffffffffu, mx1, off));
        }
        float mn0 = fmaxf(m0, mx0), mn1 = fmaxf(m1, mx1);
        float cr0 = __expf(m0 - mn0), cr1 = __expf(m1 - mn1);
        m0 = mn0; m1 = mn1;

        float s0 = 0.0f, s1 = 0.0f;
        #pragma unroll
        for (int j = 0; j < 8; j++) {
            S[j][0] = __expf(S[j][0] - mn0); s0 += S[j][0];
            S[j][1] = __expf(S[j][1] - mn0); s0 += S[j][1];
            S[j][2] = __expf(S[j][2] - mn1); s1 += S[j][2];
            S[j][3] = __expf(S[j][3] - mn1); s1 += S[j][3];
        }
        #pragma unroll
        for (int off = 1; off <= 2; off <<= 1) {
            s0 += __shfl_xor_sync(0xffffffffu, s0, off);
            s1 += __shfl_xor_sync(0xffffffffu, s1, off);
        }
        l0 = l0 * cr0 + s0;
        l1 = l1 * cr1 + s1;

        #pragma unroll
        for (int j = 0; j < 16; j++) {
            O[j][0] *= cr0; O[j][1] *= cr0;
            O[j][2] *= cr1; O[j][3] *= cr1;
        }

        uint32_t ph[4][4], pl[4][4];
        #pragma unroll
        for (int c = 0; c < 4; c++) {
            #pragma unroll
            for (int half = 0; half < 2; half++) {
                const float* sv = S[2 * c + half];
                __nv_bfloat16 h0 = __float2bfloat16(sv[0]);
                __nv_bfloat16 h1 = __float2bfloat16(sv[1]);
                __nv_bfloat16 h2 = __float2bfloat16(sv[2]);
                __nv_bfloat16 h3 = __float2bfloat16(sv[3]);
                ph[c][2 * half + 0] = packbf(h0, h1);
                ph[c][2 * half + 1] = packbf(h2, h3);
                pl[c][2 * half + 0] = packbf(
                    __float2bfloat16(sv[0] - __bfloat162float(h0)),
                    __float2bfloat16(sv[1] - __bfloat162float(h1)));
                pl[c][2 * half + 1] = packbf(
                    __float2bfloat16(sv[2] - __bfloat162float(h2)),
                    __float2bfloat16(sv[3] - __bfloat162float(h3)));
            }
        }

        #pragma unroll
        for (int c = 0; c < 4; c++) {
            #pragma unroll
            for (int jg = 0; jg < 8; jg++) {
                uint32_t vh[4], vl[4];
                uint32_t va = kb + VHOF + (uint32_t)(16 * c * QSTR) + v_lrow + 32 * jg;
                ldsm4t(va, vh);
                ldsm4t(va + (VLOF - VHOF), vl);
                mma_bf16(O[2 * jg],     ph[c], vh[0], vh[1]);
                mma_bf16(O[2 * jg],     ph[c], vl[0], vl[1]);
                mma_bf16(O[2 * jg],     pl[c], vh[0], vh[1]);
                mma_bf16(O[2 * jg + 1], ph[c], vh[2], vh[3]);
                mma_bf16(O[2 * jg + 1], ph[c], vl[2], vl[3]);
                mma_bf16(O[2 * jg + 1], pl[c], vh[2], vh[3]);
            }
        }

        if (t + 1 < NN / 64) {
            CPA_WAIT(0);
            __syncthreads();
        }
    }

    {
        float inv0 = 1.0f / l0, inv1 = 1.0f / l1;
        size_t gr0 = (size_t)bid * 128 + R + (lane >> 2);
        size_t gr1 = gr0 + 8;
        int colb = (lane & 3) * 2;
        #pragma unroll
        for (int j = 0; j < 16; j++) {
            int col = 8 * j + colb;
            *(float2*)&out[gr0 * 128 + col] = make_float2(O[j][0] * inv0, O[j][1] * inv0);
            *(float2*)&out[gr1 * 128 + col] = make_float2(O[j][2] * inv1, O[j][3] * inv1);
        }
    }
}

// ---------------------------------------------------------------------------
extern "C" void kernel_launch(void* const* d_in, const int* in_sizes, int n_in,
                              void* d_out, int out_size)
{
    (void)in_sizes; (void)n_in; (void)out_size;
    const float* x  = (const float*)d_in[0];
    const float* Wq = (const float*)d_in[1];
    const float* bq = (const float*)d_in[2];
    const float* Wk = (const float*)d_in[3];
    const float* bk = (const float*)d_in[4];
    const float* Wv = (const float*)d_in[5];
    const float* bv = (const float*)d_in[6];
    float* out = (float*)d_out;

    cudaFuncSetAttribute(proj_mma_kernel,
                         cudaFuncAttributeMaxDynamicSharedMemorySize, PSM_TOTAL);
    cudaFuncSetAttribute(attn_mma_kernel,
                         cudaFuncAttributeMaxDynamicSharedMemorySize, SM_TOTAL);

    split_w_kernel<<<96, 512>>>(Wq, Wk, Wv);
    proj_mma_kernel<<<BB * NN / 128, 256, PSM_TOTAL>>>(x, bq, bk, bv);
    attn_mma_kernel<<<BB * NN / 128, 256, SM_TOTAL>>>(out);
}

// round 5
// speedup vs baseline: 6.1952x; 1.3417x over previous
#include <cuda_runtime.h>
#include <cuda_bf16.h>
#include <cuda_fp16.h>
#include <math.h>
#include <stdint.h>

#define BB 4
#define NN 4096
#define CC 128

// Pre-split bf16 hi/lo q,k; single-fp16 v.
__device__ __nv_bfloat16 g_qh[BB * NN * CC];
__device__ __nv_bfloat16 g_ql[BB * NN * CC];
__device__ __nv_bfloat16 g_kh[BB * NN * CC];
__device__ __nv_bfloat16 g_kl[BB * NN * CC];
__device__ __half        g_vf[BB * NN * CC];

// Pre-split weights: [which][d*128+c]
__device__ __nv_bfloat16 g_wh[3][CC * CC];
__device__ __nv_bfloat16 g_wl[3][CC * CC];

// ---------------------------------------------------------------------------
// PTX helpers (compute_103-baseline features only)
// ---------------------------------------------------------------------------
__device__ __forceinline__ uint32_t smem_u32(const void* p) {
    uint32_t a;
    asm("{ .reg .u64 t; cvta.to.shared.u64 t, %1; cvt.u32.u64 %0, t; }"
        : "=r"(a) : "l"(p));
    return a;
}
__device__ __forceinline__ void ldsm4(uint32_t a, uint32_t r[4]) {
    asm volatile("ldmatrix.sync.aligned.m8n8.x4.shared.b16 {%0,%1,%2,%3}, [%4];"
        : "=r"(r[0]), "=r"(r[1]), "=r"(r[2]), "=r"(r[3]) : "r"(a));
}
__device__ __forceinline__ void ldsm4t(uint32_t a, uint32_t r[4]) {
    asm volatile("ldmatrix.sync.aligned.m8n8.x4.trans.shared.b16 {%0,%1,%2,%3}, [%4];"
        : "=r"(r[0]), "=r"(r[1]), "=r"(r[2]), "=r"(r[3]) : "r"(a));
}
__device__ __forceinline__ void mma_bf16(float c[4], const uint32_t a[4],
                                         uint32_t b0, uint32_t b1) {
    asm volatile(
        "mma.sync.aligned.m16n8k16.row.col.f32.bf16.bf16.f32 "
        "{%0,%1,%2,%3}, {%4,%5,%6,%7}, {%8,%9}, {%0,%1,%2,%3};"
        : "+f"(c[0]), "+f"(c[1]), "+f"(c[2]), "+f"(c[3])
        : "r"(a[0]), "r"(a[1]), "r"(a[2]), "r"(a[3]), "r"(b0), "r"(b1));
}
__device__ __forceinline__ void mma_f16(float c[4], const uint32_t a[4],
                                        uint32_t b0, uint32_t b1) {
    asm volatile(
        "mma.sync.aligned.m16n8k16.row.col.f32.f16.f16.f32 "
        "{%0,%1,%2,%3}, {%4,%5,%6,%7}, {%8,%9}, {%0,%1,%2,%3};"
        : "+f"(c[0]), "+f"(c[1]), "+f"(c[2]), "+f"(c[3])
        : "r"(a[0]), "r"(a[1]), "r"(a[2]), "r"(a[3]), "r"(b0), "r"(b1));
}
__device__ __forceinline__ void cpa16(uint32_t dst, const void* src) {
    asm volatile("cp.async.cg.shared.global [%0], [%1], 16;" :: "r"(dst), "l"(src));
}
#define CPA_COMMIT() asm volatile("cp.async.commit_group;" ::: "memory")
#define CPA_WAIT(n)  asm volatile("cp.async.wait_group %0;" :: "n"(n) : "memory")

__device__ __forceinline__ uint32_t packbf(__nv_bfloat16 a, __nv_bfloat16 b) {
    return (uint32_t)__bfloat16_as_ushort(a)
         | ((uint32_t)__bfloat16_as_ushort(b) << 16);
}
__device__ __forceinline__ uint32_t packh(__half a, __half b) {
    return (uint32_t)__half_as_ushort(a)
         | ((uint32_t)__half_as_ushort(b) << 16);
}

#define QSTR 272   // smem row stride (bytes): conflict-free ldmatrix

// ---------------------------------------------------------------------------
// Setup: split the three weight matrices into bf16 hi/lo.
// ---------------------------------------------------------------------------
__global__ __launch_bounds__(512) void split_w_kernel(
    const float* __restrict__ Wq,
    const float* __restrict__ Wk,
    const float* __restrict__ Wv)
{
    int idx = blockIdx.x * 512 + threadIdx.x;   // 0 .. 49151
    int which = idx >> 14;
    int i = idx & 16383;
    const float* W = (which == 0) ? Wq : (which == 1) ? Wk : Wv;
    float v = W[i];
    __nv_bfloat16 hi = __float2bfloat16(v);
    g_wh[which][i] = hi;
    g_wl[which][i] = __float2bfloat16(v - __bfloat162float(hi));
}

// ---------------------------------------------------------------------------
// Fused tensor-core projection: q,k = split(gelu(..)); v = fp16(gelu(..))
// ---------------------------------------------------------------------------
#define PSM_XH 0
#define PSM_XL 34816
#define PSM_W0 69632            // {hi, lo} buffer 0
#define PSM_W1 139264           // {hi, lo} buffer 1
#define PSM_B  208896           // 3 x 128 floats
#define PSM_TOTAL (PSM_B + 1536)

template<bool SPLIT>
__device__ __forceinline__ void proj_compute(
    uint32_t sb, uint32_t wbuf, const float* bias_s,
    __nv_bfloat16* __restrict__ oh, __nv_bfloat16* __restrict__ ol,
    __half* __restrict__ of,
    int row0, int lane, uint32_t a_lrow, uint32_t b_lrow)
{
    float acc[16][4];
    #pragma unroll
    for (int j = 0; j < 16; j++)
        #pragma unroll
        for (int q = 0; q < 4; q++) acc[j][q] = 0.0f;

    #pragma unroll
    for (int c = 0; c < 8; c++) {
        uint32_t ah[4], al[4];
        ldsm4(sb + PSM_XH + a_lrow + 32 * c, ah);
        ldsm4(sb + PSM_XL + a_lrow + 32 * c, al);
        #pragma unroll
        for (int jg = 0; jg < 8; jg++) {
            uint32_t bh[4], bl[4];
            uint32_t ba = wbuf + (uint32_t)(jg * 16 * QSTR) + b_lrow + 32 * c;
            ldsm4(ba, bh);
            ldsm4(ba + 34816, bl);
            mma_bf16(acc[2 * jg],     ah, bh[0], bh[1]);
            mma_bf16(acc[2 * jg],     ah, bl[0], bl[1]);
            mma_bf16(acc[2 * jg],     al, bh[0], bh[1]);
            mma_bf16(acc[2 * jg + 1], ah, bh[2], bh[3]);
            mma_bf16(acc[2 * jg + 1], ah, bl[2], bl[3]);
            mma_bf16(acc[2 * jg + 1], al, bh[2], bh[3]);
        }
    }

    int r0 = row0 + (lane >> 2);
    int r1 = r0 + 8;
    int colb = (lane & 3) * 2;
    #pragma unroll
    for (int j = 0; j < 16; j++) {
        int col = 8 * j + colb;
        float b0 = bias_s[col], b1 = bias_s[col + 1];
        float v00 = acc[j][0] + b0, v01 = acc[j][1] + b1;
        float v10 = acc[j][2] + b0, v11 = acc[j][3] + b1;
        float g00 = 0.5f * v00 * (1.0f + erff(v00 * 0.70710678f));
        float g01 = 0.5f * v01 * (1.0f + erff(v01 * 0.70710678f));
        float g10 = 0.5f * v10 * (1.0f + erff(v10 * 0.70710678f));
        float g11 = 0.5f * v11 * (1.0f + erff(v11 * 0.70710678f));
        if (SPLIT) {
            __nv_bfloat16 h00 = __float2bfloat16(g00);
            __nv_bfloat16 h01 = __float2bfloat16(g01);
            __nv_bfloat16 h10 = __float2bfloat16(g10);
            __nv_bfloat16 h11 = __float2bfloat16(g11);
            *(uint32_t*)(oh + (size_t)r0 * 128 + col) = packbf(h00, h01);
            *(uint32_t*)(oh + (size_t)r1 * 128 + col) = packbf(h10, h11);
            *(uint32_t*)(ol + (size_t)r0 * 128 + col) = packbf(
                __float2bfloat16(g00 - __bfloat162float(h00)),
                __float2bfloat16(g01 - __bfloat162float(h01)));
            *(uint32_t*)(ol + (size_t)r1 * 128 + col) = packbf(
                __float2bfloat16(g10 - __bfloat162float(h10)),
                __float2bfloat16(g11 - __bfloat162float(h11)));
        } else {
            *(uint32_t*)(of + (size_t)r0 * 128 + col) =
                packh(__float2half_rn(g00), __float2half_rn(g01));
            *(uint32_t*)(of + (size_t)r1 * 128 + col) =
                packh(__float2half_rn(g10), __float2half_rn(g11));
        }
    }
}

__global__ __launch_bounds__(256, 1) void proj_mma_kernel(
    const float* __restrict__ x,
    const float* __restrict__ bq,
    const float* __restrict__ bk,
    const float* __restrict__ bv)
{
    extern __shared__ char sm[];
    const uint32_t sb = smem_u32(sm);
    const int tid = threadIdx.x;
    const int w = tid >> 5;
    const int lane = tid & 31;
    const int row0 = blockIdx.x * 128;

    #pragma unroll
    for (int i = 0; i < 8; i++) {
        int cid = tid + i * 256;
        int r = cid >> 4, c = cid & 15;
        uint32_t d = (uint32_t)(r * QSTR + c * 16);
        int g = r * 128 + c * 8;
        cpa16(sb + PSM_W0 + d,         (const char*)g_wh[0] + g * 2);
        cpa16(sb + PSM_W0 + 34816 + d, (const char*)g_wl[0] + g * 2);
    }
    CPA_COMMIT();
    #pragma unroll
    for (int i = 0; i < 8; i++) {
        int cid = tid + i * 256;
        int r = cid >> 4, c = cid & 15;
        uint32_t d = (uint32_t)(r * QSTR + c * 16);
        int g = r * 128 + c * 8;
        cpa16(sb + PSM_W1 + d,         (const char*)g_wh[1] + g * 2);
        cpa16(sb + PSM_W1 + 34816 + d, (const char*)g_wl[1] + g * 2);
    }
    CPA_COMMIT();

    {
        const float4* xg = (const float4*)(x + (size_t)row0 * 128);
        #pragma unroll
        for (int i = 0; i < 16; i++) {
            int i4 = tid + i * 256;
            int r = i4 >> 5, c = (i4 & 31) << 2;
            float4 v = xg[i4];
            uint32_t d = (uint32_t)(r * QSTR + c * 2);
            __nv_bfloat16 hx = __float2bfloat16(v.x);
            __nv_bfloat16 hy = __float2bfloat16(v.y);
            __nv_bfloat16 hz = __float2bfloat16(v.z);
            __nv_bfloat16 hw = __float2bfloat16(v.w);
            *(uint32_t*)(sm + PSM_XH + d)     = packbf(hx, hy);
            *(uint32_t*)(sm + PSM_XH + d + 4) = packbf(hz, hw);
            *(uint32_t*)(sm + PSM_XL + d) = packbf(
                __float2bfloat16(v.x - __bfloat162float(hx)),
                __float2bfloat16(v.y - __bfloat162float(hy)));
            *(uint32_t*)(sm + PSM_XL + d + 4) = packbf(
                __float2bfloat16(v.z - __bfloat162float(hz)),
                __float2bfloat16(v.w - __bfloat162float(hw)));
        }
        float* bias_s = (float*)(sm + PSM_B);
        if (tid < 128)      bias_s[tid] = bq[tid];
        else if (tid < 256) bias_s[tid] = bk[tid - 128];
        if (tid < 128)      bias_s[256 + tid] = bv[tid];
    }

    const int R = w * 16;
    const uint32_t a_lrow = (uint32_t)((R + (lane & 15)) * QSTR + ((lane >> 4) << 4));
    const uint32_t b_lrow = (uint32_t)(((lane & 7) + ((lane >> 4) << 3)) * QSTR
                                       + (((lane >> 3) & 1) << 4));
    const float* bias_s = (const float*)(sm + PSM_B);

    CPA_WAIT(1);
    __syncthreads();
    proj_compute<true>(sb, sb + PSM_W0, bias_s, g_qh, g_ql, nullptr,
                       row0 + R, lane, a_lrow, b_lrow);
    __syncthreads();

    #pragma unroll
    for (int i = 0; i < 8; i++) {
        int cid = tid + i * 256;
        int r = cid >> 4, c = cid & 15;
        uint32_t d = (uint32_t)(r * QSTR + c * 16);
        int g = r * 128 + c * 8;
        cpa16(sb + PSM_W0 + d,         (const char*)g_wh[2] + g * 2);
        cpa16(sb + PSM_W0 + 34816 + d, (const char*)g_wl[2] + g * 2);
    }
    CPA_COMMIT();

    CPA_WAIT(1);
    __syncthreads();
    proj_compute<true>(sb, sb + PSM_W1, bias_s + 128, g_kh, g_kl, nullptr,
                       row0 + R, lane, a_lrow, b_lrow);

    CPA_WAIT(0);
    __syncthreads();
    proj_compute<false>(sb, sb + PSM_W0, bias_s + 256, nullptr, nullptr, g_vf,
                        row0 + R, lane, a_lrow, b_lrow);
}

// ---------------------------------------------------------------------------
// Flash attention: S = 3-pass bf16 split; PV = single-pass fp16.
// ---------------------------------------------------------------------------
#define SM_QH 0
#define SM_QL 34816
#define SM_KV 69632
#define STG   52224             // kh + kl + v(fp16), each 64*272
#define KHOF  0
#define KLOF  17408
#define VOF   34816
#define SM_TOTAL (SM_KV + 2 * STG)   // 174080

__global__ __launch_bounds__(256, 1) void attn_mma_kernel(float* __restrict__ out)
{
    extern __shared__ char sm[];
    const uint32_t sb = smem_u32(sm);
    const int tid = threadIdx.x;
    const int w = tid >> 5;
    const int lane = tid & 31;

    const int bid = blockIdx.x;
    const int batch = bid >> 5;
    const size_t qoff = (size_t)bid * 128 * CC;
    const size_t kvoff = (size_t)batch * NN * CC;

    #pragma unroll
    for (int i = 0; i < 8; i++) {
        int cid = tid + i * 256;
        int r = cid >> 4, c = cid & 15;
        uint32_t d = (uint32_t)(r * QSTR + c * 16);
        cpa16(sb + SM_QH + d, g_qh + qoff + r * 128 + c * 8);
        cpa16(sb + SM_QL + d, g_ql + qoff + r * 128 + c * 8);
    }
    {
        uint32_t base = sb + SM_KV;
        #pragma unroll
        for (int i = 0; i < 4; i++) {
            int cid = tid + i * 256;
            int r = cid >> 4, c = cid & 15;
            uint32_t d = base + r * QSTR + c * 16;
            size_t g = kvoff + (size_t)r * 128 + c * 8;
            cpa16(d + KHOF, g_kh + g);
            cpa16(d + KLOF, g_kl + g);
            cpa16(d + VOF,  g_vf + g);
        }
    }
    CPA_COMMIT();

    float O[16][4];
    #pragma unroll
    for (int j = 0; j < 16; j++)
        #pragma unroll
        for (int q = 0; q < 4; q++) O[j][q] = 0.0f;
    float m0 = -1e30f, m1 = -1e30f, l0 = 0.0f, l1 = 0.0f;

    const int R = w * 16;
    const uint32_t q_lrow = (uint32_t)((R + (lane & 15)) * QSTR + ((lane >> 4) << 4));
    const uint32_t k_lrow = (uint32_t)(((lane & 7) + ((lane >> 4) << 3)) * QSTR
                                       + (((lane >> 3) & 1) << 4));
    const uint32_t v_lrow = (uint32_t)(((lane & 7) + (((lane >> 3) & 1) << 3)) * QSTR
                                       + ((lane >> 4) << 4));

    CPA_WAIT(0);
    __syncthreads();

    for (int t = 0; t < NN / 64; t++) {
        if (t + 1 < NN / 64) {
            uint32_t base = sb + SM_KV + ((t + 1) & 1) * STG;
            size_t gkv = kvoff + (size_t)(t + 1) * 64 * 128;
            #pragma unroll
            for (int i = 0; i < 4; i++) {
                int cid = tid + i * 256;
                int r = cid >> 4, c = cid & 15;
                uint32_t d = base + r * QSTR + c * 16;
                size_t g = gkv + (size_t)r * 128 + c * 8;
                cpa16(d + KHOF, g_kh + g);
                cpa16(d + KLOF, g_kl + g);
                cpa16(d + VOF,  g_vf + g);
            }
            CPA_COMMIT();
        }

        const uint32_t kb = sb + SM_KV + (t & 1) * STG;

        float S[8][4];
        #pragma unroll
        for (int j = 0; j < 8; j++)
            #pragma unroll
            for (int q = 0; q < 4; q++) S[j][q] = 0.0f;

        #pragma unroll
        for (int c = 0; c < 8; c++) {
            uint32_t aQh[4], aQl[4];
            ldsm4(sb + SM_QH + q_lrow + 32 * c, aQh);
            ldsm4(sb + SM_QL + q_lrow + 32 * c, aQl);
            #pragma unroll
            for (int jg = 0; jg < 4; jg++) {
                uint32_t bh[4], bl[4];
                uint32_t ka = kb + KHOF + (uint32_t)(jg * 16 * QSTR) + k_lrow + 32 * c;
                ldsm4(ka, bh);
                ldsm4(ka + (KLOF - KHOF), bl);
                mma_bf16(S[2 * jg],     aQh, bh[0], bh[1]);
                mma_bf16(S[2 * jg],     aQh, bl[0], bl[1]);
                mma_bf16(S[2 * jg],     aQl, bh[0], bh[1]);
                mma_bf16(S[2 * jg + 1], aQh, bh[2], bh[3]);
                mma_bf16(S[2 * jg + 1], aQh, bl[2], bl[3]);
                mma_bf16(S[2 * jg + 1], aQl, bh[2], bh[3]);
            }
        }

        float mx0 = S[0][0], mx1 = S[0][2];
        #pragma unroll
        for (int j = 0; j < 8; j++) {
            mx0 = fmaxf(mx0, fmaxf(S[j][0], S[j][1]));
            mx1 = fmaxf(mx1, fmaxf(S[j][2], S[j][3]));
        }
        #pragma unroll
        for (int off = 1; off <= 2; off <<= 1) {
            mx0 = fmaxf(mx0, __shfl_xor_sync(0xffffffffu, mx0, off));
            mx1 = fmaxf(mx1, __shfl_xor_sync(0xffffffffu, mx1, off));
        }
        float mn0 = fmaxf(m0, mx0), mn1 = fmaxf(m1, mx1);
        float cr0 = __expf(m0 - mn0), cr1 = __expf(m1 - mn1);
        m0 = mn0; m1 = mn1;

        float s0 = 0.0f, s1 = 0.0f;
        #pragma unroll
        for (int j = 0; j < 8; j++) {
            S[j][0] = __expf(S[j][0] - mn0); s0 += S[j][0];
            S[j][1] = __expf(S[j][1] - mn0); s0 += S[j][1];
            S[j][2] = __expf(S[j][2] - mn1); s1 += S[j][2];
            S[j][3] = __expf(S[j][3] - mn1); s1 += S[j][3];
        }
        #pragma unroll
        for (int off = 1; off <= 2; off <<= 1) {
            s0 += __shfl_xor_sync(0xffffffffu, s0, off);
            s1 += __shfl_xor_sync(0xffffffffu, s1, off);
        }
        l0 = l0 * cr0 + s0;
        l1 = l1 * cr1 + s1;

        #pragma unroll
        for (int j = 0; j < 16; j++) {
            O[j][0] *= cr0; O[j][1] *= cr0;
            O[j][2] *= cr1; O[j][3] *= cr1;
        }

        // pack P into fp16 A-fragments
        uint32_t ph[4][4];
        #pragma unroll
        for (int c = 0; c < 4; c++) {
            #pragma unroll
            for (int half = 0; half < 2; half++) {
                const float* sv = S[2 * c + half];
                ph[c][2 * half + 0] = packh(__float2half_rn(sv[0]),
                                            __float2half_rn(sv[1]));
                ph[c][2 * half + 1] = packh(__float2half_rn(sv[2]),
                                            __float2half_rn(sv[3]));
            }
        }

        // O += P V (single fp16 pass); V transposed free via ldmatrix.trans
        #pragma unroll
        for (int c = 0; c < 4; c++) {
            #pragma unroll
            for (int jg = 0; jg < 8; jg++) {
                uint32_t vh[4];
                uint32_t va = kb + VOF + (uint32_t)(16 * c * QSTR) + v_lrow + 32 * jg;
                ldsm4t(va, vh);
                mma_f16(O[2 * jg],     ph[c], vh[0], vh[1]);
                mma_f16(O[2 * jg + 1], ph[c], vh[2], vh[3]);
            }
        }

        if (t + 1 < NN / 64) {
            CPA_WAIT(0);
            __syncthreads();
        }
    }

    {
        float inv0 = 1.0f / l0, inv1 = 1.0f / l1;
        size_t gr0 = (size_t)bid * 128 + R + (lane >> 2);
        size_t gr1 = gr0 + 8;
        int colb = (lane & 3) * 2;
        #pragma unroll
        for (int j = 0; j < 16; j++) {
            int col = 8 * j + colb;
            *(float2*)&out[gr0 * 128 + col] = make_float2(O[j][0] * inv0, O[j][1] * inv0);
            *(float2*)&out[gr1 * 128 + col] = make_float2(O[j][2] * inv1, O[j][3] * inv1);
        }
    }
}

// ---------------------------------------------------------------------------
extern "C" void kernel_launch(void* const* d_in, const int* in_sizes, int n_in,
                              void* d_out, int out_size)
{
    (void)in_sizes; (void)n_in; (void)out_size;
    const float* x  = (const float*)d_in[0];
    const float* Wq = (const float*)d_in[1];
    const float* bq = (const float*)d_in[2];
    const float* Wk = (const float*)d_in[3];
    const float* bk = (const float*)d_in[4];
    const float* Wv = (const float*)d_in[5];
    const float* bv = (const float*)d_in[6];
    float* out = (float*)d_out;

    cudaFuncSetAttribute(proj_mma_kernel,
                         cudaFuncAttributeMaxDynamicSharedMemorySize, PSM_TOTAL);
    cudaFuncSetAttribute(attn_mma_kernel,
                         cudaFuncAttributeMaxDynamicSharedMemorySize, SM_TOTAL);

    split_w_kernel<<<96, 512>>>(Wq, Wk, Wv);
    proj_mma_kernel<<<BB * NN / 128, 256, PSM_TOTAL>>>(x, bq, bk, bv);
    attn_mma_kernel<<<BB * NN / 128, 256, SM_TOTAL>>>(out);
}

// round 6
// speedup vs baseline: 9.0691x; 1.4639x over previous
#include <cuda_runtime.h>
#include <cuda_bf16.h>
#include <cuda_fp16.h>
#include <math.h>
#include <stdint.h>

#define BB 4
#define NN 4096
#define CC 128

// fp16 q,k,v (single precision-level; S/PV error budget analyzed above)
__device__ __half g_qf[BB * NN * CC];
__device__ __half g_kf[BB * NN * CC];
__device__ __half g_vf[BB * NN * CC];

// Pre-split weights for accurate projection: [which][d*128+c]
__device__ __nv_bfloat16 g_wh[3][CC * CC];
__device__ __nv_bfloat16 g_wl[3][CC * CC];

// ---------------------------------------------------------------------------
// PTX helpers (compute_103-baseline features only)
// ---------------------------------------------------------------------------
__device__ __forceinline__ uint32_t smem_u32(const void* p) {
    uint32_t a;
    asm("{ .reg .u64 t; cvta.to.shared.u64 t, %1; cvt.u32.u64 %0, t; }"
        : "=r"(a) : "l"(p));
    return a;
}
__device__ __forceinline__ void ldsm4(uint32_t a, uint32_t r[4]) {
    asm volatile("ldmatrix.sync.aligned.m8n8.x4.shared.b16 {%0,%1,%2,%3}, [%4];"
        : "=r"(r[0]), "=r"(r[1]), "=r"(r[2]), "=r"(r[3]) : "r"(a));
}
__device__ __forceinline__ void ldsm4t(uint32_t a, uint32_t r[4]) {
    asm volatile("ldmatrix.sync.aligned.m8n8.x4.trans.shared.b16 {%0,%1,%2,%3}, [%4];"
        : "=r"(r[0]), "=r"(r[1]), "=r"(r[2]), "=r"(r[3]) : "r"(a));
}
__device__ __forceinline__ void mma_bf16(float c[4], const uint32_t a[4],
                                         uint32_t b0, uint32_t b1) {
    asm volatile(
        "mma.sync.aligned.m16n8k16.row.col.f32.bf16.bf16.f32 "
        "{%0,%1,%2,%3}, {%4,%5,%6,%7}, {%8,%9}, {%0,%1,%2,%3};"
        : "+f"(c[0]), "+f"(c[1]), "+f"(c[2]), "+f"(c[3])
        : "r"(a[0]), "r"(a[1]), "r"(a[2]), "r"(a[3]), "r"(b0), "r"(b1));
}
__device__ __forceinline__ void mma_f16(float c[4], const uint32_t a[4],
                                        uint32_t b0, uint32_t b1) {
    asm volatile(
        "mma.sync.aligned.m16n8k16.row.col.f32.f16.f16.f32 "
        "{%0,%1,%2,%3}, {%4,%5,%6,%7}, {%8,%9}, {%0,%1,%2,%3};"
        : "+f"(c[0]), "+f"(c[1]), "+f"(c[2]), "+f"(c[3])
        : "r"(a[0]), "r"(a[1]), "r"(a[2]), "r"(a[3]), "r"(b0), "r"(b1));
}
__device__ __forceinline__ void cpa16(uint32_t dst, const void* src) {
    asm volatile("cp.async.cg.shared.global [%0], [%1], 16;" :: "r"(dst), "l"(src));
}
#define CPA_COMMIT() asm volatile("cp.async.commit_group;" ::: "memory")
#define CPA_WAIT(n)  asm volatile("cp.async.wait_group %0;" :: "n"(n) : "memory")

__device__ __forceinline__ uint32_t packbf(__nv_bfloat16 a, __nv_bfloat16 b) {
    return (uint32_t)__bfloat16_as_ushort(a)
         | ((uint32_t)__bfloat16_as_ushort(b) << 16);
}
__device__ __forceinline__ uint32_t packh(__half a, __half b) {
    return (uint32_t)__half_as_ushort(a)
         | ((uint32_t)__half_as_ushort(b) << 16);
}

#define QSTR 272   // smem row stride (bytes): conflict-free ldmatrix

// ---------------------------------------------------------------------------
// Setup: split the three weight matrices into bf16 hi/lo.
// ---------------------------------------------------------------------------
__global__ __launch_bounds__(512) void split_w_kernel(
    const float* __restrict__ Wq,
    const float* __restrict__ Wk,
    const float* __restrict__ Wv)
{
    int idx = blockIdx.x * 512 + threadIdx.x;   // 0 .. 49151
    int which = idx >> 14;
    int i = idx & 16383;
    const float* W = (which == 0) ? Wq : (which == 1) ? Wk : Wv;
    float v = W[i];
    __nv_bfloat16 hi = __float2bfloat16(v);
    g_wh[which][i] = hi;
    g_wl[which][i] = __float2bfloat16(v - __bfloat162float(hi));
}

// ---------------------------------------------------------------------------
// Fused tensor-core projection: q,k,v = fp16(gelu(x W^T + b))
// Internal compute: 3-pass bf16 split (accurate). 128 CTAs x 256 threads.
// ---------------------------------------------------------------------------
#define PSM_XH 0
#define PSM_XL 34816
#define PSM_W0 69632            // {hi, lo} buffer 0
#define PSM_W1 139264           // {hi, lo} buffer 1
#define PSM_B  208896           // 3 x 128 floats
#define PSM_TOTAL (PSM_B + 1536)

__device__ __forceinline__ void proj_compute(
    uint32_t sb, uint32_t wbuf, const float* bias_s,
    __half* __restrict__ of,
    int row0, int lane, uint32_t a_lrow, uint32_t b_lrow)
{
    float acc[16][4];
    #pragma unroll
    for (int j = 0; j < 16; j++)
        #pragma unroll
        for (int q = 0; q < 4; q++) acc[j][q] = 0.0f;

    #pragma unroll
    for (int c = 0; c < 8; c++) {
        uint32_t ah[4], al[4];
        ldsm4(sb + PSM_XH + a_lrow + 32 * c, ah);
        ldsm4(sb + PSM_XL + a_lrow + 32 * c, al);
        #pragma unroll
        for (int jg = 0; jg < 8; jg++) {
            uint32_t bh[4], bl[4];
            uint32_t ba = wbuf + (uint32_t)(jg * 16 * QSTR) + b_lrow + 32 * c;
            ldsm4(ba, bh);
            ldsm4(ba + 34816, bl);
            mma_bf16(acc[2 * jg],     ah, bh[0], bh[1]);
            mma_bf16(acc[2 * jg],     ah, bl[0], bl[1]);
            mma_bf16(acc[2 * jg],     al, bh[0], bh[1]);
            mma_bf16(acc[2 * jg + 1], ah, bh[2], bh[3]);
            mma_bf16(acc[2 * jg + 1], ah, bl[2], bl[3]);
            mma_bf16(acc[2 * jg + 1], al, bh[2], bh[3]);
        }
    }

    int r0 = row0 + (lane >> 2);
    int r1 = r0 + 8;
    int colb = (lane & 3) * 2;
    #pragma unroll
    for (int j = 0; j < 16; j++) {
        int col = 8 * j + colb;
        float b0 = bias_s[col], b1 = bias_s[col + 1];
        float v00 = acc[j][0] + b0, v01 = acc[j][1] + b1;
        float v10 = acc[j][2] + b0, v11 = acc[j][3] + b1;
        float g00 = 0.5f * v00 * (1.0f + erff(v00 * 0.70710678f));
        float g01 = 0.5f * v01 * (1.0f + erff(v01 * 0.70710678f));
        float g10 = 0.5f * v10 * (1.0f + erff(v10 * 0.70710678f));
        float g11 = 0.5f * v11 * (1.0f + erff(v11 * 0.70710678f));
        *(uint32_t*)(of + (size_t)r0 * 128 + col) =
            packh(__float2half_rn(g00), __float2half_rn(g01));
        *(uint32_t*)(of + (size_t)r1 * 128 + col) =
            packh(__float2half_rn(g10), __float2half_rn(g11));
    }
}

__global__ __launch_bounds__(256, 1) void proj_mma_kernel(
    const float* __restrict__ x,
    const float* __restrict__ bq,
    const float* __restrict__ bk,
    const float* __restrict__ bv)
{
    extern __shared__ char sm[];
    const uint32_t sb = smem_u32(sm);
    const int tid = threadIdx.x;
    const int w = tid >> 5;
    const int lane = tid & 31;
    const int row0 = blockIdx.x * 128;

    #pragma unroll
    for (int i = 0; i < 8; i++) {
        int cid = tid + i * 256;
        int r = cid >> 4, c = cid & 15;
        uint32_t d = (uint32_t)(r * QSTR + c * 16);
        int g = r * 128 + c * 8;
        cpa16(sb + PSM_W0 + d,         (const char*)g_wh[0] + g * 2);
        cpa16(sb + PSM_W0 + 34816 + d, (const char*)g_wl[0] + g * 2);
    }
    CPA_COMMIT();
    #pragma unroll
    for (int i = 0; i < 8; i++) {
        int cid = tid + i * 256;
        int r = cid >> 4, c = cid & 15;
        uint32_t d = (uint32_t)(r * QSTR + c * 16);
        int g = r * 128 + c * 8;
        cpa16(sb + PSM_W1 + d,         (const char*)g_wh[1] + g * 2);
        cpa16(sb + PSM_W1 + 34816 + d, (const char*)g_wl[1] + g * 2);
    }
    CPA_COMMIT();

    {
        const float4* xg = (const float4*)(x + (size_t)row0 * 128);
        #pragma unroll
        for (int i = 0; i < 16; i++) {
            int i4 = tid + i * 256;
            int r = i4 >> 5, c = (i4 & 31) << 2;
            float4 v = xg[i4];
            uint32_t d = (uint32_t)(r * QSTR + c * 2);
            __nv_bfloat16 hx = __float2bfloat16(v.x);
            __nv_bfloat16 hy = __float2bfloat16(v.y);
            __nv_bfloat16 hz = __float2bfloat16(v.z);
            __nv_bfloat16 hw = __float2bfloat16(v.w);
            *(uint32_t*)(sm + PSM_XH + d)     = packbf(hx, hy);
            *(uint32_t*)(sm + PSM_XH + d + 4) = packbf(hz, hw);
            *(uint32_t*)(sm + PSM_XL + d) = packbf(
                __float2bfloat16(v.x - __bfloat162float(hx)),
                __float2bfloat16(v.y - __bfloat162float(hy)));
            *(uint32_t*)(sm + PSM_XL + d + 4) = packbf(
                __float2bfloat16(v.z - __bfloat162float(hz)),
                __float2bfloat16(v.w - __bfloat162float(hw)));
        }
        float* bias_s = (float*)(sm + PSM_B);
        if (tid < 128)      bias_s[tid] = bq[tid];
        else if (tid < 256) bias_s[tid] = bk[tid - 128];
        if (tid < 128)      bias_s[256 + tid] = bv[tid];
    }

    const int R = w * 16;
    const uint32_t a_lrow = (uint32_t)((R + (lane & 15)) * QSTR + ((lane >> 4) << 4));
    const uint32_t b_lrow = (uint32_t)(((lane & 7) + ((lane >> 4) << 3)) * QSTR
                                       + (((lane >> 3) & 1) << 4));
    const float* bias_s = (const float*)(sm + PSM_B);

    CPA_WAIT(1);
    __syncthreads();
    proj_compute(sb, sb + PSM_W0, bias_s, g_qf, row0 + R, lane, a_lrow, b_lrow);
    __syncthreads();

    #pragma unroll
    for (int i = 0; i < 8; i++) {
        int cid = tid + i * 256;
        int r = cid >> 4, c = cid & 15;
        uint32_t d = (uint32_t)(r * QSTR + c * 16);
        int g = r * 128 + c * 8;
        cpa16(sb + PSM_W0 + d,         (const char*)g_wh[2] + g * 2);
        cpa16(sb + PSM_W0 + 34816 + d, (const char*)g_wl[2] + g * 2);
    }
    CPA_COMMIT();

    CPA_WAIT(1);
    __syncthreads();
    proj_compute(sb, sb + PSM_W1, bias_s + 128, g_kf, row0 + R, lane, a_lrow, b_lrow);

    CPA_WAIT(0);
    __syncthreads();
    proj_compute(sb, sb + PSM_W0, bias_s + 256, g_vf, row0 + R, lane, a_lrow, b_lrow);
}

// ---------------------------------------------------------------------------
// Flash attention: S = single-pass fp16; PV = single-pass fp16.
// 256 CTAs x 128 threads (64 q rows each, 2 CTAs/SM), Q frags hoisted to regs.
// ---------------------------------------------------------------------------
#define SM_QF 0                 // 64*272 = 17408
#define SM_KV 17408
#define KOF   0
#define VOF   17408
#define STG   34816             // K + V per stage
#define ASM_TOTAL (SM_KV + 2 * STG)   // 87040

__global__ __launch_bounds__(128, 2) void attn_mma_kernel(float* __restrict__ out)
{
    extern __shared__ char sm[];
    const uint32_t sb = smem_u32(sm);
    const int tid = threadIdx.x;
    const int w = tid >> 5;           // 0..3
    const int lane = tid & 31;

    const int bid = blockIdx.x;       // 256 CTAs, 64 q rows each
    const int batch = bid >> 6;
    const size_t qoff = (size_t)bid * 64 * CC;
    const size_t kvoff = (size_t)batch * NN * CC;

    // stage Q (64x128 fp16) + KV tile 0
    #pragma unroll
    for (int i = 0; i < 8; i++) {
        int cid = tid + i * 128;      // 1024 chunks
        int r = cid >> 4, c = cid & 15;
        cpa16(sb + SM_QF + (uint32_t)(r * QSTR + c * 16),
              g_qf + qoff + r * 128 + c * 8);
    }
    #pragma unroll
    for (int i = 0; i < 8; i++) {
        int cid = tid + i * 128;
        int r = cid >> 4, c = cid & 15;
        uint32_t d = sb + SM_KV + (uint32_t)(r * QSTR + c * 16);
        size_t g = kvoff + (size_t)r * 128 + c * 8;
        cpa16(d + KOF, g_kf + g);
        cpa16(d + VOF, g_vf + g);
    }
    CPA_COMMIT();

    float O[16][4];
    #pragma unroll
    for (int j = 0; j < 16; j++)
        #pragma unroll
        for (int q = 0; q < 4; q++) O[j][q] = 0.0f;
    float m0 = -1e30f, m1 = -1e30f, l0 = 0.0f, l1 = 0.0f;

    const int R = w * 16;
    const uint32_t q_lrow = (uint32_t)((R + (lane & 15)) * QSTR + ((lane >> 4) << 4));
    const uint32_t k_lrow = (uint32_t)(((lane & 7) + ((lane >> 4) << 3)) * QSTR
                                       + (((lane >> 3) & 1) << 4));
    const uint32_t v_lrow = (uint32_t)(((lane & 7) + (((lane >> 3) & 1) << 3)) * QSTR
                                       + ((lane >> 4) << 4));

    CPA_WAIT(0);
    __syncthreads();

    // hoist Q fragments into registers (reused across all 64 key tiles)
    uint32_t qf[8][4];
    #pragma unroll
    for (int c = 0; c < 8; c++)
        ldsm4(sb + SM_QF + q_lrow + 32 * c, qf[c]);

    for (int t = 0; t < NN / 64; t++) {
        if (t + 1 < NN / 64) {
            uint32_t base = sb + SM_KV + ((t + 1) & 1) * STG;
            size_t gkv = kvoff + (size_t)(t + 1) * 64 * 128;
            #pragma unroll
            for (int i = 0; i < 8; i++) {
                int cid = tid + i * 128;
                int r = cid >> 4, c = cid & 15;
                uint32_t d = base + (uint32_t)(r * QSTR + c * 16);
                size_t g = gkv + (size_t)r * 128 + c * 8;
                cpa16(d + KOF, g_kf + g);
                cpa16(d + VOF, g_vf + g);
            }
            CPA_COMMIT();
        }

        const uint32_t kb = sb + SM_KV + (t & 1) * STG;

        // ---- S = Q K^T, single fp16 pass
        float S[8][4];
        #pragma unroll
        for (int j = 0; j < 8; j++)
            #pragma unroll
            for (int q = 0; q < 4; q++) S[j][q] = 0.0f;

        #pragma unroll
        for (int c = 0; c < 8; c++) {
            #pragma unroll
            for (int jg = 0; jg < 4; jg++) {
                uint32_t bh[4];
                ldsm4(kb + KOF + (uint32_t)(jg * 16 * QSTR) + k_lrow + 32 * c, bh);
                mma_f16(S[2 * jg],     qf[c], bh[0], bh[1]);
                mma_f16(S[2 * jg + 1], qf[c], bh[2], bh[3]);
            }
        }

        // ---- online softmax
        float mx0 = S[0][0], mx1 = S[0][2];
        #pragma unroll
        for (int j = 0; j < 8; j++) {
            mx0 = fmaxf(mx0, fmaxf(S[j][0], S[j][1]));
            mx1 = fmaxf(mx1, fmaxf(S[j][2], S[j][3]));
        }
        #pragma unroll
        for (int off = 1; off <= 2; off <<= 1) {
            mx0 = fmaxf(mx0, __shfl_xor_sync(0xffffffffu, mx0, off));
            mx1 = fmaxf(mx1, __shfl_xor_sync(0xffffffffu, mx1, off));
        }
        float mn0 = fmaxf(m0, mx0), mn1 = fmaxf(m1, mx1);
        float cr0 = __expf(m0 - mn0), cr1 = __expf(m1 - mn1);
        m0 = mn0; m1 = mn1;

        float s0 = 0.0f, s1 = 0.0f;
        #pragma unroll
        for (int j = 0; j < 8; j++) {
            S[j][0] = __expf(S[j][0] - mn0); s0 += S[j][0];
            S[j][1] = __expf(S[j][1] - mn0); s0 += S[j][1];
            S[j][2] = __expf(S[j][2] - mn1); s1 += S[j][2];
            S[j][3] = __expf(S[j][3] - mn1); s1 += S[j][3];
        }
        #pragma unroll
        for (int off = 1; off <= 2; off <<= 1) {
            s0 += __shfl_xor_sync(0xffffffffu, s0, off);
            s1 += __shfl_xor_sync(0xffffffffu, s1, off);
        }
        l0 = l0 * cr0 + s0;
        l1 = l1 * cr1 + s1;

        #pragma unroll
        for (int j = 0; j < 16; j++) {
            O[j][0] *= cr0; O[j][1] *= cr0;
            O[j][2] *= cr1; O[j][3] *= cr1;
        }

        // ---- pack P into fp16 A-fragments
        uint32_t ph[4][4];
        #pragma unroll
        for (int c = 0; c < 4; c++) {
            #pragma unroll
            for (int half = 0; half < 2; half++) {
                const float* sv = S[2 * c + half];
                ph[c][2 * half + 0] = packh(__float2half_rn(sv[0]),
                                            __float2half_rn(sv[1]));
                ph[c][2 * half + 1] = packh(__float2half_rn(sv[2]),
                                            __float2half_rn(sv[3]));
            }
        }

        // ---- O += P V (single fp16 pass), V transposed free via ldmatrix.trans
        #pragma unroll
        for (int c = 0; c < 4; c++) {
            #pragma unroll
            for (int jg = 0; jg < 8; jg++) {
                uint32_t vh[4];
                ldsm4t(kb + VOF + (uint32_t)(16 * c * QSTR) + v_lrow + 32 * jg, vh);
                mma_f16(O[2 * jg],     ph[c], vh[0], vh[1]);
                mma_f16(O[2 * jg + 1], ph[c], vh[2], vh[3]);
            }
        }

        if (t + 1 < NN / 64) {
            CPA_WAIT(0);
            __syncthreads();
        }
    }

    // ---- epilogue
    {
        float inv0 = 1.0f / l0, inv1 = 1.0f / l1;
        size_t gr0 = (size_t)bid * 64 + R + (lane >> 2);
        size_t gr1 = gr0 + 8;
        int colb = (lane & 3) * 2;
        #pragma unroll
        for (int j = 0; j < 16; j++) {
            int col = 8 * j + colb;
            *(float2*)&out[gr0 * 128 + col] = make_float2(O[j][0] * inv0, O[j][1] * inv0);
            *(float2*)&out[gr1 * 128 + col] = make_float2(O[j][2] * inv1, O[j][3] * inv1);
        }
    }
}

// ---------------------------------------------------------------------------
extern "C" void kernel_launch(void* const* d_in, const int* in_sizes, int n_in,
                              void* d_out, int out_size)
{
    (void)in_sizes; (void)n_in; (void)out_size;
    const float* x  = (const float*)d_in[0];
    const float* Wq = (const float*)d_in[1];
    const float* bq = (const float*)d_in[2];
    const float* Wk = (const float*)d_in[3];
    const float* bk = (const float*)d_in[4];
    const float* Wv = (const float*)d_in[5];
    const float* bv = (const float*)d_in[6];
    float* out = (float*)d_out;

    cudaFuncSetAttribute(proj_mma_kernel,
                         cudaFuncAttributeMaxDynamicSharedMemorySize, PSM_TOTAL);
    cudaFuncSetAttribute(attn_mma_kernel,
                         cudaFuncAttributeMaxDynamicSharedMemorySize, ASM_TOTAL);

    split_w_kernel<<<96, 512>>>(Wq, Wk, Wv);
    proj_mma_kernel<<<BB * NN / 128, 256, PSM_TOTAL>>>(x, bq, bk, bv);
    attn_mma_kernel<<<BB * NN / 64, 128, ASM_TOTAL>>>(out);
}

// round 7
// speedup vs baseline: 9.5245x; 1.0502x over previous
#include <cuda_runtime.h>
#include <cuda_bf16.h>
#include <cuda_fp16.h>
#include <math.h>
#include <stdint.h>

#define BB 4
#define NN 4096
#define CC 128

// fp16 q,k,v. q is pre-scaled by log2(e) so attention works in base-2 domain.
__device__ __half g_qf[BB * NN * CC];
__device__ __half g_kf[BB * NN * CC];
__device__ __half g_vf[BB * NN * CC];

// ---------------------------------------------------------------------------
// PTX helpers (compute_103-baseline features only)
// ---------------------------------------------------------------------------
__device__ __forceinline__ uint32_t smem_u32(const void* p) {
    uint32_t a;
    asm("{ .reg .u64 t; cvta.to.shared.u64 t, %1; cvt.u32.u64 %0, t; }"
        : "=r"(a) : "l"(p));
    return a;
}
__device__ __forceinline__ void ldsm4(uint32_t a, uint32_t r[4]) {
    asm volatile("ldmatrix.sync.aligned.m8n8.x4.shared.b16 {%0,%1,%2,%3}, [%4];"
        : "=r"(r[0]), "=r"(r[1]), "=r"(r[2]), "=r"(r[3]) : "r"(a));
}
__device__ __forceinline__ void ldsm4t(uint32_t a, uint32_t r[4]) {
    asm volatile("ldmatrix.sync.aligned.m8n8.x4.trans.shared.b16 {%0,%1,%2,%3}, [%4];"
        : "=r"(r[0]), "=r"(r[1]), "=r"(r[2]), "=r"(r[3]) : "r"(a));
}
__device__ __forceinline__ void mma_bf16(float c[4], const uint32_t a[4],
                                         uint32_t b0, uint32_t b1) {
    asm volatile(
        "mma.sync.aligned.m16n8k16.row.col.f32.bf16.bf16.f32 "
        "{%0,%1,%2,%3}, {%4,%5,%6,%7}, {%8,%9}, {%0,%1,%2,%3};"
        : "+f"(c[0]), "+f"(c[1]), "+f"(c[2]), "+f"(c[3])
        : "r"(a[0]), "r"(a[1]), "r"(a[2]), "r"(a[3]), "r"(b0), "r"(b1));
}
__device__ __forceinline__ void mma_f16(float c[4], const uint32_t a[4],
                                        uint32_t b0, uint32_t b1) {
    asm volatile(
        "mma.sync.aligned.m16n8k16.row.col.f32.f16.f16.f32 "
        "{%0,%1,%2,%3}, {%4,%5,%6,%7}, {%8,%9}, {%0,%1,%2,%3};"
        : "+f"(c[0]), "+f"(c[1]), "+f"(c[2]), "+f"(c[3])
        : "r"(a[0]), "r"(a[1]), "r"(a[2]), "r"(a[3]), "r"(b0), "r"(b1));
}
__device__ __forceinline__ void cpa16(uint32_t dst, const void* src) {
    asm volatile("cp.async.cg.shared.global [%0], [%1], 16;" :: "r"(dst), "l"(src));
}
#define CPA_COMMIT() asm volatile("cp.async.commit_group;" ::: "memory")
#define CPA_WAIT(n)  asm volatile("cp.async.wait_group %0;" :: "n"(n) : "memory")

__device__ __forceinline__ uint32_t packbf(__nv_bfloat16 a, __nv_bfloat16 b) {
    return (uint32_t)__bfloat16_as_ushort(a)
         | ((uint32_t)__bfloat16_as_ushort(b) << 16);
}
__device__ __forceinline__ uint32_t packh(__half a, __half b) {
    return (uint32_t)__half_as_ushort(a)
         | ((uint32_t)__half_as_ushort(b) << 16);
}
__device__ __forceinline__ float ex2(float x) {
    float y;
    asm("ex2.approx.ftz.f32 %0, %1;" : "=f"(y) : "f"(x));
    return y;
}

#define QSTR 272   // smem row stride (bytes): conflict-free ldmatrix
#define LOG2E 1.4426950408889634f

// ---------------------------------------------------------------------------
// Fused tensor-core projection: q,k,v = fp16(gelu(x W^T + b)); q scaled by
// log2(e). Weights converted fp32 -> bf16 hi/lo in-CTA (no setup kernel).
// Internal compute: 3-pass bf16 split. 128 CTAs x 256 threads.
// ---------------------------------------------------------------------------
#define PSM_XH 0
#define PSM_XL 34816
#define PSM_WH 69632
#define PSM_WL 104448
#define PSM_B  139264           // 3 x 128 floats
#define PSM_TOTAL (PSM_B + 1536)

__device__ __forceinline__ void proj_compute(
    uint32_t sb, const float* bias_s, float oscale,
    __half* __restrict__ of,
    int row0, int lane, uint32_t a_lrow, uint32_t b_lrow)
{
    float acc[16][4];
    #pragma unroll
    for (int j = 0; j < 16; j++)
        #pragma unroll
        for (int q = 0; q < 4; q++) acc[j][q] = 0.0f;

    #pragma unroll
    for (int c = 0; c < 8; c++) {
        uint32_t ah[4], al[4];
        ldsm4(sb + PSM_XH + a_lrow + 32 * c, ah);
        ldsm4(sb + PSM_XL + a_lrow + 32 * c, al);
        #pragma unroll
        for (int jg = 0; jg < 8; jg++) {
            uint32_t bh[4], bl[4];
            uint32_t ba = sb + PSM_WH + (uint32_t)(jg * 16 * QSTR) + b_lrow + 32 * c;
            ldsm4(ba, bh);
            ldsm4(ba + (PSM_WL - PSM_WH), bl);
            mma_bf16(acc[2 * jg],     ah, bh[0], bh[1]);
            mma_bf16(acc[2 * jg],     ah, bl[0], bl[1]);
            mma_bf16(acc[2 * jg],     al, bh[0], bh[1]);
            mma_bf16(acc[2 * jg + 1], ah, bh[2], bh[3]);
            mma_bf16(acc[2 * jg + 1], ah, bl[2], bl[3]);
            mma_bf16(acc[2 * jg + 1], al, bh[2], bh[3]);
        }
    }

    int r0 = row0 + (lane >> 2);
    int r1 = r0 + 8;
    int colb = (lane & 3) * 2;
    #pragma unroll
    for (int j = 0; j < 16; j++) {
        int col = 8 * j + colb;
        float b0 = bias_s[col], b1 = bias_s[col + 1];
        float v00 = acc[j][0] + b0, v01 = acc[j][1] + b1;
        float v10 = acc[j][2] + b0, v11 = acc[j][3] + b1;
        float g00 = 0.5f * v00 * (1.0f + erff(v00 * 0.70710678f)) * oscale;
        float g01 = 0.5f * v01 * (1.0f + erff(v01 * 0.70710678f)) * oscale;
        float g10 = 0.5f * v10 * (1.0f + erff(v10 * 0.70710678f)) * oscale;
        float g11 = 0.5f * v11 * (1.0f + erff(v11 * 0.70710678f)) * oscale;
        *(uint32_t*)(of + (size_t)r0 * 128 + col) =
            packh(__float2half_rn(g00), __float2half_rn(g01));
        *(uint32_t*)(of + (size_t)r1 * 128 + col) =
            packh(__float2half_rn(g10), __float2half_rn(g11));
    }
}

// convert a 128x128 fp32 matrix tile (global) into bf16 hi/lo smem (ldmatrix
// layout); 256 threads, 16 float4 each.
__device__ __forceinline__ void stage_split(const float* __restrict__ src,
                                            char* __restrict__ smh,
                                            char* __restrict__ sml, int tid)
{
    const float4* sg = (const float4*)src;
    #pragma unroll
    for (int i = 0; i < 16; i++) {
        int i4 = tid + i * 256;
        int r = i4 >> 5, c = (i4 & 31) << 2;
        float4 v = sg[i4];
        uint32_t d = (uint32_t)(r * QSTR + c * 2);
        __nv_bfloat16 hx = __float2bfloat16(v.x);
        __nv_bfloat16 hy = __float2bfloat16(v.y);
        __nv_bfloat16 hz = __float2bfloat16(v.z);
        __nv_bfloat16 hw = __float2bfloat16(v.w);
        *(uint32_t*)(smh + d)     = packbf(hx, hy);
        *(uint32_t*)(smh + d + 4) = packbf(hz, hw);
        *(uint32_t*)(sml + d) = packbf(
            __float2bfloat16(v.x - __bfloat162float(hx)),
            __float2bfloat16(v.y - __bfloat162float(hy)));
        *(uint32_t*)(sml + d + 4) = packbf(
            __float2bfloat16(v.z - __bfloat162float(hz)),
            __float2bfloat16(v.w - __bfloat162float(hw)));
    }
}

__global__ __launch_bounds__(256, 1) void proj_mma_kernel(
    const float* __restrict__ x,
    const float* __restrict__ Wq,
    const float* __restrict__ Wk,
    const float* __restrict__ Wv,
    const float* __restrict__ bq,
    const float* __restrict__ bk,
    const float* __restrict__ bv)
{
    extern __shared__ char sm[];
    const uint32_t sb = smem_u32(sm);
    const int tid = threadIdx.x;
    const int w = tid >> 5;
    const int lane = tid & 31;
    const int row0 = blockIdx.x * 128;

    // stage x tile (fp32 -> bf16 hi/lo) and biases
    stage_split(x + (size_t)row0 * 128, sm + PSM_XH, sm + PSM_XL, tid);
    {
        float* bias_s = (float*)(sm + PSM_B);
        if (tid < 128)      bias_s[tid] = bq[tid];
        else if (tid < 256) bias_s[tid] = bk[tid - 128];
        if (tid < 128)      bias_s[256 + tid] = bv[tid];
    }

    const int R = w * 16;
    const uint32_t a_lrow = (uint32_t)((R + (lane & 15)) * QSTR + ((lane >> 4) << 4));
    const uint32_t b_lrow = (uint32_t)(((lane & 7) + ((lane >> 4) << 3)) * QSTR
                                       + (((lane >> 3) & 1) << 4));
    const float* bias_s = (const float*)(sm + PSM_B);

    // q (scaled by log2 e)
    stage_split(Wq, sm + PSM_WH, sm + PSM_WL, tid);
    __syncthreads();
    proj_compute(sb, bias_s, LOG2E, g_qf, row0 + R, lane, a_lrow, b_lrow);
    __syncthreads();

    // k
    stage_split(Wk, sm + PSM_WH, sm + PSM_WL, tid);
    __syncthreads();
    proj_compute(sb, bias_s + 128, 1.0f, g_kf, row0 + R, lane, a_lrow, b_lrow);
    __syncthreads();

    // v
    stage_split(Wv, sm + PSM_WH, sm + PSM_WL, tid);
    __syncthreads();
    proj_compute(sb, bias_s + 256, 1.0f, g_vf, row0 + R, lane, a_lrow, b_lrow);
}

// ---------------------------------------------------------------------------
// Flash attention: S = single-pass fp16 (base-2 logits); PV = single-pass fp16.
// 256 CTAs x 128 threads (64 q rows each, 2 CTAs/SM), Q frags hoisted to regs.
// ---------------------------------------------------------------------------
#define SM_QF 0                 // 64*272 = 17408
#define SM_KV 17408
#define KOF   0
#define VOF   17408
#define STG   34816             // K + V per stage
#define ASM_TOTAL (SM_KV + 2 * STG)   // 87040

__global__ __launch_bounds__(128, 2) void attn_mma_kernel(float* __restrict__ out)
{
    extern __shared__ char sm[];
    const uint32_t sb = smem_u32(sm);
    const int tid = threadIdx.x;
    const int w = tid >> 5;           // 0..3
    const int lane = tid & 31;

    const int bid = blockIdx.x;       // 256 CTAs, 64 q rows each
    const int batch = bid >> 6;
    const size_t qoff = (size_t)bid * 64 * CC;
    const size_t kvoff = (size_t)batch * NN * CC;

    // stage Q (64x128 fp16) + KV tile 0
    #pragma unroll
    for (int i = 0; i < 8; i++) {
        int cid = tid + i * 128;      // 1024 chunks
        int r = cid >> 4, c = cid & 15;
        cpa16(sb + SM_QF + (uint32_t)(r * QSTR + c * 16),
              g_qf + qoff + r * 128 + c * 8);
    }
    #pragma unroll
    for (int i = 0; i < 8; i++) {
        int cid = tid + i * 128;
        int r = cid >> 4, c = cid & 15;
        uint32_t d = sb + SM_KV + (uint32_t)(r * QSTR + c * 16);
        size_t g = kvoff + (size_t)r * 128 + c * 8;
        cpa16(d + KOF, g_kf + g);
        cpa16(d + VOF, g_vf + g);
    }
    CPA_COMMIT();

    float O[16][4];
    #pragma unroll
    for (int j = 0; j < 16; j++)
        #pragma unroll
        for (int q = 0; q < 4; q++) O[j][q] = 0.0f;
    float m0 = -1e30f, m1 = -1e30f, l0 = 0.0f, l1 = 0.0f;

    const int R = w * 16;
    const uint32_t q_lrow = (uint32_t)((R + (lane & 15)) * QSTR + ((lane >> 4) << 4));
    const uint32_t k_lrow = (uint32_t)(((lane & 7) + ((lane >> 4) << 3)) * QSTR
                                       + (((lane >> 3) & 1) << 4));
    const uint32_t v_lrow = (uint32_t)(((lane & 7) + (((lane >> 3) & 1) << 3)) * QSTR
                                       + ((lane >> 4) << 4));

    CPA_WAIT(0);
    __syncthreads();

    // hoist Q fragments into registers (reused across all 64 key tiles)
    uint32_t qf[8][4];
    #pragma unroll
    for (int c = 0; c < 8; c++)
        ldsm4(sb + SM_QF + q_lrow + 32 * c, qf[c]);

    for (int t = 0; t < NN / 64; t++) {
        if (t + 1 < NN / 64) {
            uint32_t base = sb + SM_KV + ((t + 1) & 1) * STG;
            size_t gkv = kvoff + (size_t)(t + 1) * 64 * 128;
            #pragma unroll
            for (int i = 0; i < 8; i++) {
                int cid = tid + i * 128;
                int r = cid >> 4, c = cid & 15;
                uint32_t d = base + (uint32_t)(r * QSTR + c * 16);
                size_t g = gkv + (size_t)r * 128 + c * 8;
                cpa16(d + KOF, g_kf + g);
                cpa16(d + VOF, g_vf + g);
            }
            CPA_COMMIT();
        }

        const uint32_t kb = sb + SM_KV + (t & 1) * STG;

        // ---- S = Q K^T, single fp16 pass (logits in log2 units)
        float S[8][4];
        #pragma unroll
        for (int j = 0; j < 8; j++)
            #pragma unroll
            for (int q = 0; q < 4; q++) S[j][q] = 0.0f;

        #pragma unroll
        for (int c = 0; c < 8; c++) {
            #pragma unroll
            for (int jg = 0; jg < 4; jg++) {
                uint32_t bh[4];
                ldsm4(kb + KOF + (uint32_t)(jg * 16 * QSTR) + k_lrow + 32 * c, bh);
                mma_f16(S[2 * jg],     qf[c], bh[0], bh[1]);
                mma_f16(S[2 * jg + 1], qf[c], bh[2], bh[3]);
            }
        }

        // ---- online softmax (base-2 domain, raw EX2)
        float mx0 = S[0][0], mx1 = S[0][2];
        #pragma unroll
        for (int j = 0; j < 8; j++) {
            mx0 = fmaxf(mx0, fmaxf(S[j][0], S[j][1]));
            mx1 = fmaxf(mx1, fmaxf(S[j][2], S[j][3]));
        }
        #pragma unroll
        for (int off = 1; off <= 2; off <<= 1) {
            mx0 = fmaxf(mx0, __shfl_xor_sync(0xffffffffu, mx0, off));
            mx1 = fmaxf(mx1, __shfl_xor_sync(0xffffffffu, mx1, off));
        }
        float mn0 = fmaxf(m0, mx0), mn1 = fmaxf(m1, mx1);
        float cr0 = ex2(m0 - mn0), cr1 = ex2(m1 - mn1);
        m0 = mn0; m1 = mn1;

        float s0 = 0.0f, s1 = 0.0f;
        #pragma unroll
        for (int j = 0; j < 8; j++) {
            S[j][0] = ex2(S[j][0] - mn0); s0 += S[j][0];
            S[j][1] = ex2(S[j][1] - mn0); s0 += S[j][1];
            S[j][2] = ex2(S[j][2] - mn1); s1 += S[j][2];
            S[j][3] = ex2(S[j][3] - mn1); s1 += S[j][3];
        }
        #pragma unroll
        for (int off = 1; off <= 2; off <<= 1) {
            s0 += __shfl_xor_sync(0xffffffffu, s0, off);
            s1 += __shfl_xor_sync(0xffffffffu, s1, off);
        }
        l0 = l0 * cr0 + s0;
        l1 = l1 * cr1 + s1;

        #pragma unroll
        for (int j = 0; j < 16; j++) {
            O[j][0] *= cr0; O[j][1] *= cr0;
            O[j][2] *= cr1; O[j][3] *= cr1;
        }

        // ---- pack P into fp16 A-fragments
        uint32_t ph[4][4];
        #pragma unroll
        for (int c = 0; c < 4; c++) {
            #pragma unroll
            for (int half = 0; half < 2; half++) {
                const float* sv = S[2 * c + half];
                ph[c][2 * half + 0] = packh(__float2half_rn(sv[0]),
                                            __float2half_rn(sv[1]));
                ph[c][2 * half + 1] = packh(__float2half_rn(sv[2]),
                                            __float2half_rn(sv[3]));
            }
        }

        // ---- O += P V (single fp16 pass), V transposed free via ldmatrix.trans
        #pragma unroll
        for (int c = 0; c < 4; c++) {
            #pragma unroll
            for (int jg = 0; jg < 8; jg++) {
                uint32_t vh[4];
                ldsm4t(kb + VOF + (uint32_t)(16 * c * QSTR) + v_lrow + 32 * jg, vh);
                mma_f16(O[2 * jg],     ph[c], vh[0], vh[1]);
                mma_f16(O[2 * jg + 1], ph[c], vh[2], vh[3]);
            }
        }

        if (t + 1 < NN / 64) {
            CPA_WAIT(0);
            __syncthreads();
        }
    }

    // ---- epilogue
    {
        float inv0 = 1.0f / l0, inv1 = 1.0f / l1;
        size_t gr0 = (size_t)bid * 64 + R + (lane >> 2);
        size_t gr1 = gr0 + 8;
        int colb = (lane & 3) * 2;
        #pragma unroll
        for (int j = 0; j < 16; j++) {
            int col = 8 * j + colb;
            *(float2*)&out[gr0 * 128 + col] = make_float2(O[j][0] * inv0, O[j][1] * inv0);
            *(float2*)&out[gr1 * 128 + col] = make_float2(O[j][2] * inv1, O[j][3] * inv1);
        }
    }
}

// ---------------------------------------------------------------------------
extern "C" void kernel_launch(void* const* d_in, const int* in_sizes, int n_in,
                              void* d_out, int out_size)
{
    (void)in_sizes; (void)n_in; (void)out_size;
    const float* x  = (const float*)d_in[0];
    const float* Wq = (const float*)d_in[1];
    const float* bq = (const float*)d_in[2];
    const float* Wk = (const float*)d_in[3];
    const float* bk = (const float*)d_in[4];
    const float* Wv = (const float*)d_in[5];
    const float* bv = (const float*)d_in[6];
    float* out = (float*)d_out;

    cudaFuncSetAttribute(proj_mma_kernel,
                         cudaFuncAttributeMaxDynamicSharedMemorySize, PSM_TOTAL);
    cudaFuncSetAttribute(attn_mma_kernel,
                         cudaFuncAttributeMaxDynamicSharedMemorySize, ASM_TOTAL);

    proj_mma_kernel<<<BB * NN / 128, 256, PSM_TOTAL>>>(x, Wq, Wk, Wv, bq, bk, bv);
    attn_mma_kernel<<<BB * NN / 64, 128, ASM_TOTAL>>>(out);
}

// round 9
// speedup vs baseline: 9.6511x; 1.0133x over previous
#include <cuda_runtime.h>
#include <cuda_bf16.h>
#include <cuda_fp16.h>
#include <math.h>
#include <stdint.h>

#define BB 4
#define NN 4096
#define CC 128

// fp16 q,k,v. q is pre-scaled by log2(e) so attention works in base-2 domain.
__device__ __half g_qf[BB * NN * CC];
__device__ __half g_kf[BB * NN * CC];
__device__ __half g_vf[BB * NN * CC];

// ---------------------------------------------------------------------------
// PTX helpers (compute_103-baseline features only)
// ---------------------------------------------------------------------------
__device__ __forceinline__ uint32_t smem_u32(const void* p) {
    uint32_t a;
    asm("{ .reg .u64 t; cvta.to.shared.u64 t, %1; cvt.u32.u64 %0, t; }"
        : "=r"(a) : "l"(p));
    return a;
}
__device__ __forceinline__ void ldsm4(uint32_t a, uint32_t r[4]) {
    asm volatile("ldmatrix.sync.aligned.m8n8.x4.shared.b16 {%0,%1,%2,%3}, [%4];"
        : "=r"(r[0]), "=r"(r[1]), "=r"(r[2]), "=r"(r[3]) : "r"(a));
}
__device__ __forceinline__ void ldsm4t(uint32_t a, uint32_t r[4]) {
    asm volatile("ldmatrix.sync.aligned.m8n8.x4.trans.shared.b16 {%0,%1,%2,%3}, [%4];"
        : "=r"(r[0]), "=r"(r[1]), "=r"(r[2]), "=r"(r[3]) : "r"(a));
}
__device__ __forceinline__ void ldsm2t(uint32_t a, uint32_t r[2]) {
    asm volatile("ldmatrix.sync.aligned.m8n8.x2.trans.shared.b16 {%0,%1}, [%2];"
        : "=r"(r[0]), "=r"(r[1]) : "r"(a));
}
__device__ __forceinline__ void mma_bf16(float c[4], const uint32_t a[4],
                                         uint32_t b0, uint32_t b1) {
    asm volatile(
        "mma.sync.aligned.m16n8k16.row.col.f32.bf16.bf16.f32 "
        "{%0,%1,%2,%3}, {%4,%5,%6,%7}, {%8,%9}, {%0,%1,%2,%3};"
        : "+f"(c[0]), "+f"(c[1]), "+f"(c[2]), "+f"(c[3])
        : "r"(a[0]), "r"(a[1]), "r"(a[2]), "r"(a[3]), "r"(b0), "r"(b1));
}
__device__ __forceinline__ void mma_f16(float c[4], const uint32_t a[4],
                                        uint32_t b0, uint32_t b1) {
    asm volatile(
        "mma.sync.aligned.m16n8k16.row.col.f32.f16.f16.f32 "
        "{%0,%1,%2,%3}, {%4,%5,%6,%7}, {%8,%9}, {%0,%1,%2,%3};"
        : "+f"(c[0]), "+f"(c[1]), "+f"(c[2]), "+f"(c[3])
        : "r"(a[0]), "r"(a[1]), "r"(a[2]), "r"(a[3]), "r"(b0), "r"(b1));
}
__device__ __forceinline__ void cpa16(uint32_t dst, const void* src) {
    asm volatile("cp.async.cg.shared.global [%0], [%1], 16;" :: "r"(dst), "l"(src));
}
#define CPA_COMMIT() asm volatile("cp.async.commit_group;" ::: "memory")
#define CPA_WAIT(n)  asm volatile("cp.async.wait_group %0;" :: "n"(n) : "memory")

__device__ __forceinline__ uint32_t packbf(__nv_bfloat16 a, __nv_bfloat16 b) {
    return (uint32_t)__bfloat16_as_ushort(a)
         | ((uint32_t)__bfloat16_as_ushort(b) << 16);
}
__device__ __forceinline__ uint32_t packh(__half a, __half b) {
    return (uint32_t)__half_as_ushort(a)
         | ((uint32_t)__half_as_ushort(b) << 16);
}
__device__ __forceinline__ float ex2(float x) {
    float y;
    asm("ex2.approx.ftz.f32 %0, %1;" : "=f"(y) : "f"(x));
    return y;
}
// pack two floats into fp16x2 (lo in low half)
__device__ __forceinline__ uint32_t cvth2(float hi, float lo) {
    uint32_t r;
    asm("cvt.rn.f16x2.f32 %0, %1, %2;" : "=r"(r) : "f"(hi), "f"(lo));
    return r;
}
__device__ __forceinline__ uint32_t ex2h2(uint32_t a) {
    uint32_t r;
    asm("ex2.approx.f16x2 %0, %1;" : "=r"(r) : "r"(a));
    return r;
}

#define QSTR 272   // smem row stride (bytes): conflict-free ldmatrix
#define LOG2E 1.4426950408889634f

// ---------------------------------------------------------------------------
// Fused tensor-core projection (unchanged from R6): q,k,v = fp16(gelu(xW^T+b));
// q scaled by log2(e). Internal compute: 3-pass bf16 split.
// ---------------------------------------------------------------------------
#define PSM_XH 0
#define PSM_XL 34816
#define PSM_WH 69632
#define PSM_WL 104448
#define PSM_B  139264
#define PSM_TOTAL (PSM_B + 1536)

__device__ __forceinline__ void proj_compute(
    uint32_t sb, const float* bias_s, float oscale,
    __half* __restrict__ of,
    int row0, int lane, uint32_t a_lrow, uint32_t b_lrow)
{
    float acc[16][4];
    #pragma unroll
    for (int j = 0; j < 16; j++)
        #pragma unroll
        for (int q = 0; q < 4; q++) acc[j][q] = 0.0f;

    #pragma unroll
    for (int c = 0; c < 8; c++) {
        uint32_t ah[4], al[4];
        ldsm4(sb + PSM_XH + a_lrow + 32 * c, ah);
        ldsm4(sb + PSM_XL + a_lrow + 32 * c, al);
        #pragma unroll
        for (int jg = 0; jg < 8; jg++) {
            uint32_t bh[4], bl[4];
            uint32_t ba = sb + PSM_WH + (uint32_t)(jg * 16 * QSTR) + b_lrow + 32 * c;
            ldsm4(ba, bh);
            ldsm4(ba + (PSM_WL - PSM_WH), bl);
            mma_bf16(acc[2 * jg],     ah, bh[0], bh[1]);
            mma_bf16(acc[2 * jg],     ah, bl[0], bl[1]);
            mma_bf16(acc[2 * jg],     al, bh[0], bh[1]);
            mma_bf16(acc[2 * jg + 1], ah, bh[2], bh[3]);
            mma_bf16(acc[2 * jg + 1], ah, bl[2], bl[3]);
            mma_bf16(acc[2 * jg + 1], al, bh[2], bh[3]);
        }
    }

    int r0 = row0 + (lane >> 2);
    int r1 = r0 + 8;
    int colb = (lane & 3) * 2;
    #pragma unroll
    for (int j = 0; j < 16; j++) {
        int col = 8 * j + colb;
        float b0 = bias_s[col], b1 = bias_s[col + 1];
        float v00 = acc[j][0] + b0, v01 = acc[j][1] + b1;
        float v10 = acc[j][2] + b0, v11 = acc[j][3] + b1;
        float g00 = 0.5f * v00 * (1.0f + erff(v00 * 0.70710678f)) * oscale;
        float g01 = 0.5f * v01 * (1.0f + erff(v01 * 0.70710678f)) * oscale;
        float g10 = 0.5f * v10 * (1.0f + erff(v10 * 0.70710678f)) * oscale;
        float g11 = 0.5f * v11 * (1.0f + erff(v11 * 0.70710678f)) * oscale;
        *(uint32_t*)(of + (size_t)r0 * 128 + col) =
            packh(__float2half_rn(g00), __float2half_rn(g01));
        *(uint32_t*)(of + (size_t)r1 * 128 + col) =
            packh(__float2half_rn(g10), __float2half_rn(g11));
    }
}

__device__ __forceinline__ void stage_split(const float* __restrict__ src,
                                            char* __restrict__ smh,
                                            char* __restrict__ sml, int tid)
{
    const float4* sg = (const float4*)src;
    #pragma unroll
    for (int i = 0; i < 16; i++) {
        int i4 = tid + i * 256;
        int r = i4 >> 5, c = (i4 & 31) << 2;
        float4 v = sg[i4];
        uint32_t d = (uint32_t)(r * QSTR + c * 2);
        __nv_bfloat16 hx = __float2bfloat16(v.x);
        __nv_bfloat16 hy = __float2bfloat16(v.y);
        __nv_bfloat16 hz = __float2bfloat16(v.z);
        __nv_bfloat16 hw = __float2bfloat16(v.w);
        *(uint32_t*)(smh + d)     = packbf(hx, hy);
        *(uint32_t*)(smh + d + 4) = packbf(hz, hw);
        *(uint32_t*)(sml + d) = packbf(
            __float2bfloat16(v.x - __bfloat162float(hx)),
            __float2bfloat16(v.y - __bfloat162float(hy)));
        *(uint32_t*)(sml + d + 4) = packbf(
            __float2bfloat16(v.z - __bfloat162float(hz)),
            __float2bfloat16(v.w - __bfloat162float(hw)));
    }
}

__global__ __launch_bounds__(256, 1) void proj_mma_kernel(
    const float* __restrict__ x,
    const float* __restrict__ Wq,
    const float* __restrict__ Wk,
    const float* __restrict__ Wv,
    const float* __restrict__ bq,
    const float* __restrict__ bk,
    const float* __restrict__ bv)
{
    extern __shared__ char sm[];
    const uint32_t sb = smem_u32(sm);
    const int tid = threadIdx.x;
    const int w = tid >> 5;
    const int lane = tid & 31;
    const int row0 = blockIdx.x * 128;

    stage_split(x + (size_t)row0 * 128, sm + PSM_XH, sm + PSM_XL, tid);
    {
        float* bias_s = (float*)(sm + PSM_B);
        if (tid < 128)      bias_s[tid] = bq[tid];
        else if (tid < 256) bias_s[tid] = bk[tid - 128];
        if (tid < 128)      bias_s[256 + tid] = bv[tid];
    }

    const int R = w * 16;
    const uint32_t a_lrow = (uint32_t)((R + (lane & 15)) * QSTR + ((lane >> 4) << 4));
    const uint32_t b_lrow = (uint32_t)(((lane & 7) + ((lane >> 4) << 3)) * QSTR
                                       + (((lane >> 3) & 1) << 4));
    const float* bias_s = (const float*)(sm + PSM_B);

    stage_split(Wq, sm + PSM_WH, sm + PSM_WL, tid);
    __syncthreads();
    proj_compute(sb, bias_s, LOG2E, g_qf, row0 + R, lane, a_lrow, b_lrow);
    __syncthreads();

    stage_split(Wk, sm + PSM_WH, sm + PSM_WL, tid);
    __syncthreads();
    proj_compute(sb, bias_s + 128, 1.0f, g_kf, row0 + R, lane, a_lrow, b_lrow);
    __syncthreads();

    stage_split(Wv, sm + PSM_WH, sm + PSM_WL, tid);
    __syncthreads();
    proj_compute(sb, bias_s + 256, 1.0f, g_vf, row0 + R, lane, a_lrow, b_lrow);
}

// ---------------------------------------------------------------------------
// Flash attention: fp16 S + PV; l via ones-column MMA; fp16x2 exp.
// 256 CTAs x 128 threads (64 q rows each, 2 CTAs/SM), Q frags in registers.
// ---------------------------------------------------------------------------
#define SM_QF 0                 // 64*272 = 17408
#define SM_KV 17408
#define KOF   0
#define VOF   17408
#define STG   34816             // K + V per stage
#define ASM_TOTAL (SM_KV + 2 * STG)   // 87040

__global__ __launch_bounds__(128, 2) void attn_mma_kernel(float* __restrict__ out)
{
    extern __shared__ char sm[];
    const uint32_t sb = smem_u32(sm);
    const int tid = threadIdx.x;
    const int w = tid >> 5;           // 0..3
    const int lane = tid & 31;

    const int bid = blockIdx.x;       // 256 CTAs, 64 q rows each
    const int batch = bid >> 6;
    const size_t qoff = (size_t)bid * 64 * CC;
    const size_t kvoff = (size_t)batch * NN * CC;

    // stage Q (64x128 fp16) + KV tile 0
    #pragma unroll
    for (int i = 0; i < 8; i++) {
        int cid = tid + i * 128;
        int r = cid >> 4, c = cid & 15;
        cpa16(sb + SM_QF + (uint32_t)(r * QSTR + c * 16),
              g_qf + qoff + r * 128 + c * 8);
    }
    #pragma unroll
    for (int i = 0; i < 8; i++) {
        int cid = tid + i * 128;
        int r = cid >> 4, c = cid & 15;
        uint32_t d = sb + SM_KV + (uint32_t)(r * QSTR + c * 16);
        size_t g = kvoff + (size_t)r * 128 + c * 8;
        cpa16(d + KOF, g_kf + g);
        cpa16(d + VOF, g_vf + g);
    }
    CPA_COMMIT();

    // ones-column for the l-sum MMA: V smem cols 128..135 (bytes 256..271),
    // never touched by cp.async staging. col128 = 1.0h, cols 129-135 = 0.
    {
        int stage = tid >> 6, r = tid & 63;
        uint4 ones = make_uint4(0x3C00u, 0u, 0u, 0u);
        *(uint4*)(sm + SM_KV + stage * STG + VOF + r * QSTR + 256) = ones;
    }

    float O[16][4];
    #pragma unroll
    for (int j = 0; j < 16; j++)
        #pragma unroll
        for (int q = 0; q < 4; q++) O[j][q] = 0.0f;
    float Ol[4] = {0.0f, 0.0f, 0.0f, 0.0f};   // l accumulator (ones column)
    float m0 = -1e30f, m1 = -1e30f;

    const int R = w * 16;
    const uint32_t q_lrow = (uint32_t)((R + (lane & 15)) * QSTR + ((lane >> 4) << 4));
    const uint32_t k_lrow = (uint32_t)(((lane & 7) + ((lane >> 4) << 3)) * QSTR
                                       + (((lane >> 3) & 1) << 4));
    const uint32_t v_lrow = (uint32_t)(((lane & 7) + (((lane >> 3) & 1) << 3)) * QSTR
                                       + ((lane >> 4) << 4));
    const uint32_t vs_lrow = (uint32_t)((lane & 15) * QSTR + 256);

    CPA_WAIT(0);
    __syncthreads();

    // hoist Q fragments into registers (reused across all 64 key tiles)
    uint32_t qf[8][4];
    #pragma unroll
    for (int c = 0; c < 8; c++)
        ldsm4(sb + SM_QF + q_lrow + 32 * c, qf[c]);

    for (int t = 0; t < NN / 64; t++) {
        if (t + 1 < NN / 64) {
            uint32_t base = sb + SM_KV + ((t + 1) & 1) * STG;
            size_t gkv = kvoff + (size_t)(t + 1) * 64 * 128;
            #pragma unroll
            for (int i = 0; i < 8; i++) {
                int cid = tid + i * 128;
                int r = cid >> 4, c = cid & 15;
                uint32_t d = base + (uint32_t)(r * QSTR + c * 16);
                size_t g = gkv + (size_t)r * 128 + c * 8;
                cpa16(d + KOF, g_kf + g);
                cpa16(d + VOF, g_vf + g);
            }
            CPA_COMMIT();
        }

        const uint32_t kb = sb + SM_KV + (t & 1) * STG;

        // ---- S = Q K^T, single fp16 pass (logits in log2 units)
        float S[8][4];
        #pragma unroll
        for (int j = 0; j < 8; j++)
            #pragma unroll
            for (int q = 0; q < 4; q++) S[j][q] = 0.0f;

        #pragma unroll
        for (int c = 0; c < 8; c++) {
            #pragma unroll
            for (int jg = 0; jg < 4; jg++) {
                uint32_t bh[4];
                ldsm4(kb + KOF + (uint32_t)(jg * 16 * QSTR) + k_lrow + 32 * c, bh);
                mma_f16(S[2 * jg],     qf[c], bh[0], bh[1]);
                mma_f16(S[2 * jg + 1], qf[c], bh[2], bh[3]);
            }
        }

        // ---- row max + rescale (skipped when no row max changed warp-wide)
        float mx0 = S[0][0], mx1 = S[0][2];
        #pragma unroll
        for (int j = 0; j < 8; j++) {
            mx0 = fmaxf(mx0, fmaxf(S[j][0], S[j][1]));
            mx1 = fmaxf(mx1, fmaxf(S[j][2], S[j][3]));
        }
        #pragma unroll
        for (int off = 1; off <= 2; off <<= 1) {
            mx0 = fmaxf(mx0, __shfl_xor_sync(0xffffffffu, mx0, off));
            mx1 = fmaxf(mx1, __shfl_xor_sync(0xffffffffu, mx1, off));
        }
        float mn0 = fmaxf(m0, mx0), mn1 = fmaxf(m1, mx1);
        if (!__all_sync(0xffffffffu, (m0 == mn0) && (m1 == mn1))) {
            float cr0 = ex2(m0 - mn0), cr1 = ex2(m1 - mn1);
            #pragma unroll
            for (int j = 0; j < 16; j++) {
                O[j][0] *= cr0; O[j][1] *= cr0;
                O[j][2] *= cr1; O[j][3] *= cr1;
            }
            Ol[0] *= cr0; Ol[1] *= cr0;
            Ol[2] *= cr1; Ol[3] *= cr1;
        }
        m0 = mn0; m1 = mn1;

        // ---- P = exp2(S - m), computed directly into fp16x2 A-fragments
        uint32_t ph[4][4];
        #pragma unroll
        for (int c = 0; c < 4; c++) {
            #pragma unroll
            for (int half = 0; half < 2; half++) {
                const float* sv = S[2 * c + half];
                ph[c][2 * half + 0] = ex2h2(cvth2(sv[1] - mn0, sv[0] - mn0));
                ph[c][2 * half + 1] = ex2h2(cvth2(sv[3] - mn1, sv[2] - mn1));
            }
        }

        // ---- O += P V  and  Ol += P 1  (single fp16 pass)
        #pragma unroll
        for (int c = 0; c < 4; c++) {
            #pragma unroll
            for (int jg = 0; jg < 8; jg++) {
                uint32_t vh[4];
                ldsm4t(kb + VOF + (uint32_t)(16 * c * QSTR) + v_lrow + 32 * jg, vh);
                mma_f16(O[2 * jg],     ph[c], vh[0], vh[1]);
                mma_f16(O[2 * jg + 1], ph[c], vh[2], vh[3]);
            }
            uint32_t vo[2];
            ldsm2t(kb + VOF + (uint32_t)(16 * c * QSTR) + vs_lrow, vo);
            mma_f16(Ol, ph[c], vo[0], vo[1]);
        }

        if (t + 1 < NN / 64) {
            CPA_WAIT(0);
            __syncthreads();
        }
    }

    // ---- epilogue: l lives in the ones-column accumulator of quad-lane 0
    {
        float l0 = __shfl_sync(0xffffffffu, Ol[0], lane & 28);
        float l1 = __shfl_sync(0xffffffffu, Ol[2], lane & 28);
        float inv0 = 1.0f / l0, inv1 = 1.0f / l1;
        size_t gr0 = (size_t)bid * 64 + R + (lane >> 2);
        size_t gr1 = gr0 + 8;
        int colb = (lane & 3) * 2;
        #pragma unroll
        for (int j = 0; j < 16; j++) {
            int col = 8 * j + colb;
            *(float2*)&out[gr0 * 128 + col] = make_float2(O[j][0] * inv0, O[j][1] * inv0);
            *(float2*)&out[gr1 * 128 + col] = make_float2(O[j][2] * inv1, O[j][3] * inv1);
        }
    }
}

// ---------------------------------------------------------------------------
extern "C" void kernel_launch(void* const* d_in, const int* in_sizes, int n_in,
                              void* d_out, int out_size)
{
    (void)in_sizes; (void)n_in; (void)out_size;
    const float* x  = (const float*)d_in[0];
    const float* Wq = (const float*)d_in[1];
    const float* bq = (const float*)d_in[2];
    const float* Wk = (const float*)d_in[3];
    const float* bk = (const float*)d_in[4];
    const float* Wv = (const float*)d_in[5];
    const float* bv = (const float*)d_in[6];
    float* out = (float*)d_out;

    cudaFuncSetAttribute(proj_mma_kernel,
                         cudaFuncAttributeMaxDynamicSharedMemorySize, PSM_TOTAL);
    cudaFuncSetAttribute(attn_mma_kernel,
                         cudaFuncAttributeMaxDynamicSharedMemorySize, ASM_TOTAL);

    proj_mma_kernel<<<BB * NN / 128, 256, PSM_TOTAL>>>(x, Wq, Wk, Wv, bq, bk, bv);
    attn_mma_kernel<<<BB * NN / 64, 128, ASM_TOTAL>>>(out);
}